// round 12
// baseline (speedup 1.0000x reference)
#include <cuda_runtime.h>
#include <cuda_bf16.h>
#include <cstdint>

// Problem constants
#define BATCH   2
#define SEQ     2048
#define HID     1024
#define NHEAD   16
#define HDIM    64
#define QKV_N   (3 * HID)     // 3072
#define M_TOT   (BATCH * SEQ) // 4096

// Scratch (device globals: allocation-free rule)
__device__ __nv_bfloat16 g_hh[(size_t)M_TOT * HID];
__device__ __nv_bfloat16 g_hl[(size_t)M_TOT * HID];
__device__ __nv_bfloat16 g_qkvh[(size_t)M_TOT * QKV_N];
__device__ __nv_bfloat16 g_qkvl[(size_t)M_TOT * QKV_N];
__device__ __nv_bfloat16 g_ctxh[(size_t)M_TOT * HID];
__device__ __nv_bfloat16 g_ctxl[(size_t)M_TOT * HID];
__device__ __nv_bfloat16 g_vTh[(size_t)BATCH * HID * SEQ];
__device__ __nv_bfloat16 g_vTl[(size_t)BATCH * HID * SEQ];
__device__ __nv_bfloat16 g_wTh[(size_t)QKV_N * HID];
__device__ __nv_bfloat16 g_wTl[(size_t)QKV_N * HID];
__device__ __nv_bfloat16 g_pTh[(size_t)HID * HID];
__device__ __nv_bfloat16 g_pTl[(size_t)HID * HID];

// ---------------------------------------------------------------------------
// Helpers
// ---------------------------------------------------------------------------
__device__ __forceinline__ void split_bf16(float a, __nv_bfloat16& h, __nv_bfloat16& l) {
    h = __float2bfloat16_rn(a);
    l = __float2bfloat16_rn(a - __bfloat162float(h));
}

__device__ __forceinline__ void pack_split(float x, float y, uint32_t& hi, uint32_t& lo) {
    __nv_bfloat16 hx, lx, hy, ly;
    split_bf16(x, hx, lx);
    split_bf16(y, hy, ly);
    __nv_bfloat162 ph = {hx, hy}, pl = {lx, ly};
    hi = *(uint32_t*)&ph;
    lo = *(uint32_t*)&pl;
}

__device__ __forceinline__ void mma_bf16(
    float& d0, float& d1, float& d2, float& d3,
    uint32_t a0, uint32_t a1, uint32_t a2, uint32_t a3,
    uint32_t b0, uint32_t b1)
{
    asm volatile(
        "mma.sync.aligned.m16n8k16.row.col.f32.bf16.bf16.f32 "
        "{%0,%1,%2,%3}, {%4,%5,%6,%7}, {%8,%9}, {%0,%1,%2,%3};"
        : "+f"(d0), "+f"(d1), "+f"(d2), "+f"(d3)
        : "r"(a0), "r"(a1), "r"(a2), "r"(a3), "r"(b0), "r"(b1));
}

__device__ __forceinline__ void ldsm_x4(uint32_t& r0, uint32_t& r1, uint32_t& r2, uint32_t& r3,
                                        uint32_t addr)
{
    asm volatile("ldmatrix.sync.aligned.m8n8.x4.shared.b16 {%0,%1,%2,%3}, [%4];"
                 : "=r"(r0), "=r"(r1), "=r"(r2), "=r"(r3) : "r"(addr));
}

__device__ __forceinline__ uint32_t smem_u32(const void* p) {
    uint32_t a;
    asm("{ .reg .u64 t; cvta.to.shared.u64 t, %1; cvt.u32.u64 %0, t; }"
        : "=r"(a) : "l"(p));
    return a;
}

__device__ __forceinline__ void cp_async16(uint32_t dst, const void* src) {
    asm volatile("cp.async.cg.shared.global [%0], [%1], 16;" :: "r"(dst), "l"(src));
}
#define CP_COMMIT() asm volatile("cp.async.commit_group;" ::: "memory")
#define CP_WAIT(n)  asm volatile("cp.async.wait_group %0;" :: "n"(n) : "memory")

// ---------------------------------------------------------------------------
// Fused prep: both weight transposes + activation split, one launch.
// blocks [0, 3072): w_attn transpose (96 x 32 tiles)
// blocks [3072, 4096): w_proj transpose (32 x 32 tiles)
// blocks [4096, 8192): hidden split (4096 blocks x 1024 floats)
// All branches use 256 threads.
// ---------------------------------------------------------------------------
__global__ __launch_bounds__(256) void prep_all(
    const float* __restrict__ hidden,
    const float* __restrict__ w_attn, const float* __restrict__ w_proj,
    __nv_bfloat16* __restrict__ hh,  __nv_bfloat16* __restrict__ hl,
    __nv_bfloat16* __restrict__ wTh, __nv_bfloat16* __restrict__ wTl,
    __nv_bfloat16* __restrict__ pTh, __nv_bfloat16* __restrict__ pTl)
{
    const int bid = blockIdx.x;
    const int tid = threadIdx.x;

    if (bid < 4096) {
        // Weight transpose branch
        __shared__ float t[32][33];
        const float* B;
        __nv_bfloat16 *Bh, *Bl;
        int n0, k0, N, K;
        if (bid < 3072) {
            B = w_attn; Bh = wTh; Bl = wTl; N = QKV_N; K = HID;
            n0 = (bid % 96) * 32; k0 = (bid / 96) * 32;
        } else {
            const int b2 = bid - 3072;
            B = w_proj; Bh = pTh; Bl = pTl; N = HID; K = HID;
            n0 = (b2 % 32) * 32; k0 = (b2 / 32) * 32;
        }
        const int x = tid & 31, y = tid >> 5; // (32, 8)
#pragma unroll
        for (int i = y; i < 32; i += 8)
            t[i][x] = B[(size_t)(k0 + i) * N + n0 + x];
        __syncthreads();
#pragma unroll
        for (int i = y; i < 32; i += 8) {
            float a = t[x][i];
            __nv_bfloat16 h, l;
            split_bf16(a, h, l);
            Bh[(size_t)(n0 + i) * K + k0 + x] = h;
            Bl[(size_t)(n0 + i) * K + k0 + x] = l;
        }
    } else {
        // Activation split branch
        const size_t i = ((size_t)(bid - 4096) * 256 + tid) * 4;
        float4 v = *(const float4*)(hidden + i);
        uint32_t h0, l0, h1, l1;
        pack_split(v.x, v.y, h0, l0);
        pack_split(v.z, v.w, h1, l1);
        uint2 ph = {h0, h1}, pl = {l0, l1};
        *(uint2*)(hh + i) = ph;
        *(uint2*)(hl + i) = pl;
    }
}

// ---------------------------------------------------------------------------
// All-bf16 cp.async GEMM with ldmatrix fragments (round-8 proven ordering).
// V-region tiles (n0 >= 2*HID when Ch!=null) written transposed to vT.
// ---------------------------------------------------------------------------
#define G_AH 0
#define G_AL 10240
#define G_BH 20480
#define G_BL 30720
#define G_STAGE 40960
#define G_SMEM (2 * G_STAGE)

__global__ __launch_bounds__(256, 2) void gemm_bf16_pipe(
    const __nv_bfloat16* __restrict__ Ah, const __nv_bfloat16* __restrict__ Al,
    const __nv_bfloat16* __restrict__ Bth, const __nv_bfloat16* __restrict__ Btl,
    const float* __restrict__ bias, float* __restrict__ C,
    __nv_bfloat16* __restrict__ Ch, __nv_bfloat16* __restrict__ Cl,
    __nv_bfloat16* __restrict__ VTh, __nv_bfloat16* __restrict__ VTl,
    int K, int N)
{
    extern __shared__ char smem[];
    const uint32_t smem_base = smem_u32(smem);

    const int tid = threadIdx.x;
    const int wid = tid >> 5;
    const int lane = tid & 31;
    const int g  = lane >> 2;
    const int c2 = (lane & 3) * 2;
    const int warp_m = wid & 1;
    const int warp_n = wid >> 1;
    const int m0 = blockIdx.y * 128;
    const int n0 = blockIdx.x * 128;
    const int wm = warp_m * 64;
    const int wn = warp_n * 32;

    const int lrA = lane & 15;
    const int lcA = (lane >> 4) * 8;
    uint32_t offA[4];
#pragma unroll
    for (int mi = 0; mi < 4; mi++)
        offA[mi] = (uint32_t)(((wm + mi * 16 + lrA) * 40 + lcA) * 2);
    uint32_t offB[2];
#pragma unroll
    for (int p = 0; p < 2; p++)
        offB[p] = (uint32_t)(((wn + p * 16 + ((lane >> 4) & 1) * 8 + (lane & 7)) * 40
                              + ((lane >> 3) & 1) * 8) * 2);

    float acc[4][4][4];
#pragma unroll
    for (int mi = 0; mi < 4; mi++)
#pragma unroll
        for (int ni = 0; ni < 4; ni++)
#pragma unroll
            for (int r = 0; r < 4; r++) acc[mi][ni][r] = 0.0f;

    auto issue = [&](int k0, int st) {
        const uint32_t sb = smem_base + st * G_STAGE;
#pragma unroll
        for (int it = 0; it < 2; it++) {
            const int idx = tid + it * 256;
            const int r = idx >> 2;
            const int q = idx & 3;
            const size_t aoff = (size_t)(m0 + r) * K + k0 + q * 8;
            const size_t boff = (size_t)(n0 + r) * K + k0 + q * 8;
            const uint32_t d = r * 80 + q * 16;
            cp_async16(sb + G_AH + d, Ah + aoff);
            cp_async16(sb + G_AL + d, Al + aoff);
            cp_async16(sb + G_BH + d, Bth + boff);
            cp_async16(sb + G_BL + d, Btl + boff);
        }
        CP_COMMIT();
    };

    const int nchunks = K >> 5;
    issue(0, 0);

    for (int ic = 0; ic < nchunks; ic++) {
        const int st = ic & 1;
        CP_WAIT(0);
        __syncthreads();
        if (ic + 1 < nchunks) issue((ic + 1) << 5, st ^ 1);

        const uint32_t sb = smem_base + st * G_STAGE;

#pragma unroll
        for (int kk = 0; kk < 32; kk += 16) {
            uint32_t ah[4][4], al[4][4];
#pragma unroll
            for (int mi = 0; mi < 4; mi++) {
                ldsm_x4(ah[mi][0], ah[mi][1], ah[mi][2], ah[mi][3],
                        sb + G_AH + offA[mi] + kk * 2);
                ldsm_x4(al[mi][0], al[mi][1], al[mi][2], al[mi][3],
                        sb + G_AL + offA[mi] + kk * 2);
            }
#pragma unroll
            for (int p = 0; p < 2; p++) {
                uint32_t bh[4], bl[4];
                ldsm_x4(bh[0], bh[1], bh[2], bh[3], sb + G_BH + offB[p] + kk * 2);
                ldsm_x4(bl[0], bl[1], bl[2], bl[3], sb + G_BL + offB[p] + kk * 2);
#pragma unroll
                for (int t = 0; t < 2; t++) {
                    const int ni = 2 * p + t;
                    const uint32_t bh0 = bh[2 * t], bh1 = bh[2 * t + 1];
                    const uint32_t bl0 = bl[2 * t], bl1 = bl[2 * t + 1];
#pragma unroll
                    for (int mi = 0; mi < 4; mi++) {
                        mma_bf16(acc[mi][ni][0], acc[mi][ni][1], acc[mi][ni][2], acc[mi][ni][3],
                                 ah[mi][0], ah[mi][1], ah[mi][2], ah[mi][3], bh0, bh1);
                        mma_bf16(acc[mi][ni][0], acc[mi][ni][1], acc[mi][ni][2], acc[mi][ni][3],
                                 ah[mi][0], ah[mi][1], ah[mi][2], ah[mi][3], bl0, bl1);
                        mma_bf16(acc[mi][ni][0], acc[mi][ni][1], acc[mi][ni][2], acc[mi][ni][3],
                                 al[mi][0], al[mi][1], al[mi][2], al[mi][3], bh0, bh1);
                    }
                }
            }
        }
    }

    if (Ch) {
        if (n0 >= 2 * HID) {
            // ---- V-region tile: transpose through SMEM, write vT [b][d][s] ----
            __syncthreads();
            __nv_bfloat16* sH = (__nv_bfloat16*)smem;              // [128][136]
            __nv_bfloat16* sL = (__nv_bfloat16*)(smem + 34816);    // [128][136]
#pragma unroll
            for (int mi = 0; mi < 4; mi++) {
                const int r0 = wm + mi * 16 + g;
#pragma unroll
                for (int ni = 0; ni < 4; ni++) {
                    const int colL = wn + ni * 8 + c2;
                    const float b0 = __ldg(bias + n0 + colL);
                    const float b1 = __ldg(bias + n0 + colL + 1);
                    __nv_bfloat16 h, l;
                    float v;
                    v = acc[mi][ni][0] + b0; split_bf16(v, h, l);
                    sH[colL * 136 + r0] = h;           sL[colL * 136 + r0] = l;
                    v = acc[mi][ni][1] + b1; split_bf16(v, h, l);
                    sH[(colL + 1) * 136 + r0] = h;     sL[(colL + 1) * 136 + r0] = l;
                    v = acc[mi][ni][2] + b0; split_bf16(v, h, l);
                    sH[colL * 136 + r0 + 8] = h;       sL[colL * 136 + r0 + 8] = l;
                    v = acc[mi][ni][3] + b1; split_bf16(v, h, l);
                    sH[(colL + 1) * 136 + r0 + 8] = h; sL[(colL + 1) * 136 + r0 + 8] = l;
                }
            }
            __syncthreads();
            const int bidx  = m0 >> 11;
            const int s0    = m0 & (SEQ - 1);
            const int dbase = n0 - 2 * HID;
#pragma unroll
            for (int it = 0; it < 8; it++) {
                const int idx = tid + it * 256;
                const int d  = idx >> 4;
                const int ch = idx & 15;
                uint4 vh = *(const uint4*)(sH + d * 136 + ch * 8);
                uint4 vl = *(const uint4*)(sL + d * 136 + ch * 8);
                const size_t dst = ((size_t)bidx * HID + dbase + d) * SEQ + s0 + ch * 8;
                *(uint4*)(VTh + dst) = vh;
                *(uint4*)(VTl + dst) = vl;
            }
        } else {
#pragma unroll
            for (int mi = 0; mi < 4; mi++) {
                const int row0 = m0 + wm + mi * 16 + g;
#pragma unroll
                for (int ni = 0; ni < 4; ni++) {
                    const int colL = wn + ni * 8 + c2;
                    const float b0 = __ldg(bias + n0 + colL);
                    const float b1 = __ldg(bias + n0 + colL + 1);
                    uint32_t h0, l0, h1, l1;
                    pack_split(acc[mi][ni][0] + b0, acc[mi][ni][1] + b1, h0, l0);
                    pack_split(acc[mi][ni][2] + b0, acc[mi][ni][3] + b1, h1, l1);
                    const size_t o0 = (size_t)row0 * N + n0 + colL;
                    const size_t o1 = (size_t)(row0 + 8) * N + n0 + colL;
                    *(uint32_t*)(Ch + o0) = h0;
                    *(uint32_t*)(Cl + o0) = l0;
                    *(uint32_t*)(Ch + o1) = h1;
                    *(uint32_t*)(Cl + o1) = l1;
                }
            }
        }
    } else {
#pragma unroll
        for (int mi = 0; mi < 4; mi++) {
            const int row0 = m0 + wm + mi * 16 + g;
#pragma unroll
            for (int ni = 0; ni < 4; ni++) {
                const int colL = wn + ni * 8 + c2;
                const float b0 = __ldg(bias + n0 + colL);
                const float b1 = __ldg(bias + n0 + colL + 1);
                float2 v0 = {acc[mi][ni][0] + b0, acc[mi][ni][1] + b1};
                float2 v1 = {acc[mi][ni][2] + b0, acc[mi][ni][3] + b1};
                *(float2*)(C + (size_t)row0 * N + n0 + colL) = v0;
                *(float2*)(C + (size_t)(row0 + 8) * N + n0 + colL) = v1;
            }
        }
    }
}

// ===========================================================================
// Flash attention: 256 q-rows per CTA, 512 threads, 3-stage cp.async pipeline
// (prefetch depth 2), mask preloaded once into SMEM.
// SMEM: 3 x 36864 stages + 8192 mask = 118784 bytes.
// ===========================================================================
#define KH_OFF   0
#define KL_OFF   9216
#define VH_OFF   18432
#define VL_OFF   27648
#define STAGE_SZ 36864
#define MASK_OFF (3 * STAGE_SZ)          // 110592
#define SMEM_TOT (MASK_OFF + SEQ * 4)    // 118784
#define NTILES   (SEQ / 64)              // 32

__global__ __launch_bounds__(512, 1) void flash_attn_tc(
    const __nv_bfloat16* __restrict__ qkvh, const __nv_bfloat16* __restrict__ qkvl,
    const __nv_bfloat16* __restrict__ vTh,  const __nv_bfloat16* __restrict__ vTl,
    const float* __restrict__ mask,
    __nv_bfloat16* __restrict__ ctxh, __nv_bfloat16* __restrict__ ctxl)
{
    extern __shared__ char smem[];
    const uint32_t smem_base = smem_u32(smem);

    const int tid  = threadIdx.x;
    const int wid  = tid >> 5;          // 0..15
    const int lane = tid & 31;
    const int g    = lane >> 2;
    const int c2   = (lane & 3) * 2;
    const int q0   = blockIdx.x * 256;
    const int h    = blockIdx.y;
    const int b    = blockIdx.z;

    const size_t row_base = (size_t)b * SEQ;
    const int hoff  = h * HDIM;
    const int khoff = HID + hoff;
    const size_t vrow_base = ((size_t)b * HID + hoff) * SEQ;

    uint32_t offKV[4];
#pragma unroll
    for (int p = 0; p < 4; p++)
        offKV[p] = (uint32_t)(((p * 16 + ((lane >> 4) & 1) * 8 + (lane & 7)) * 72
                               + ((lane >> 3) & 1) * 8) * 2);

    // Mask: whole row once (2048 floats)
    float* sMaskAll = (float*)(smem + MASK_OFF);
#pragma unroll
    for (int it = 0; it < 4; it++)
        sMaskAll[tid + it * 512] = mask[(size_t)b * SEQ + tid + it * 512];

    // Q fragments
    uint32_t qh[4][4], ql[4][4];
    {
        const __nv_bfloat16* qr0 = qkvh + (row_base + q0 + wid * 16 + g) * QKV_N + hoff;
        const __nv_bfloat16* qr1 = qr0 + 8 * QKV_N;
        const __nv_bfloat16* lr0 = qkvl + (row_base + q0 + wid * 16 + g) * QKV_N + hoff;
        const __nv_bfloat16* lr1 = lr0 + 8 * QKV_N;
#pragma unroll
        for (int s = 0; s < 4; s++) {
            qh[s][0] = *(const uint32_t*)(qr0 + s * 16 + c2);
            qh[s][1] = *(const uint32_t*)(qr1 + s * 16 + c2);
            qh[s][2] = *(const uint32_t*)(qr0 + s * 16 + 8 + c2);
            qh[s][3] = *(const uint32_t*)(qr1 + s * 16 + 8 + c2);
            ql[s][0] = *(const uint32_t*)(lr0 + s * 16 + c2);
            ql[s][1] = *(const uint32_t*)(lr1 + s * 16 + c2);
            ql[s][2] = *(const uint32_t*)(lr0 + s * 16 + 8 + c2);
            ql[s][3] = *(const uint32_t*)(lr1 + s * 16 + 8 + c2);
        }
    }

    float o[8][4];
#pragma unroll
    for (int j = 0; j < 8; j++)
#pragma unroll
        for (int r = 0; r < 4; r++) o[j][r] = 0.0f;
    float m0 = -1e30f, m1 = -1e30f, l0 = 0.0f, l1 = 0.0f;

    auto issue_tile = [&](int k0, int st) {
        const uint32_t sb = smem_base + st * STAGE_SZ;
#pragma unroll
        for (int it = 0; it < 2; it++) {
            const int idx = tid + it * 512;
            const int bufsel = idx >> 9;
            const int j = idx & 511;
            const int r = j >> 3;
            const int q = j & 7;
            const __nv_bfloat16* src =
                (bufsel ? qkvl : qkvh) + (row_base + k0 + r) * QKV_N + khoff + q * 8;
            cp_async16(sb + (bufsel ? KL_OFF : KH_OFF) + r * 144 + q * 16, src);
        }
#pragma unroll
        for (int it = 0; it < 2; it++) {
            const int idx = tid + it * 512;
            const int bufsel = idx >> 9;
            const int j = idx & 511;
            const int r = j >> 3;
            const int q = j & 7;
            const __nv_bfloat16* src =
                (bufsel ? vTl : vTh) + vrow_base + (size_t)r * SEQ + k0 + q * 8;
            cp_async16(sb + (bufsel ? VL_OFF : VH_OFF) + r * 144 + q * 16, src);
        }
        CP_COMMIT();
    };

    issue_tile(0, 0);
    issue_tile(64, 1);

    for (int i = 0; i < NTILES; i++) {
        const int st = i % 3;
        if (i + 1 < NTILES) { CP_WAIT(1); } else { CP_WAIT(0); }
        __syncthreads();
        if (i + 2 < NTILES) issue_tile((i + 2) * 64, (i + 2) % 3);

        const uint32_t sbKh = smem_base + st * STAGE_SZ + KH_OFF;
        const uint32_t sbKl = smem_base + st * STAGE_SZ + KL_OFF;
        const uint32_t sbVh = smem_base + st * STAGE_SZ + VH_OFF;
        const uint32_t sbVl = smem_base + st * STAGE_SZ + VL_OFF;
        const float* sMask = sMaskAll + i * 64;

        float sc[8][4];
#pragma unroll
        for (int j = 0; j < 8; j++)
#pragma unroll
            for (int r = 0; r < 4; r++) sc[j][r] = 0.0f;

#pragma unroll
        for (int s = 0; s < 4; s++) {
#pragma unroll
            for (int p = 0; p < 4; p++) {
                uint32_t bh[4], bl[4];
                ldsm_x4(bh[0], bh[1], bh[2], bh[3], sbKh + offKV[p] + s * 32);
                ldsm_x4(bl[0], bl[1], bl[2], bl[3], sbKl + offKV[p] + s * 32);
#pragma unroll
                for (int t = 0; t < 2; t++) {
                    const int j = 2 * p + t;
                    mma_bf16(sc[j][0], sc[j][1], sc[j][2], sc[j][3],
                             qh[s][0], qh[s][1], qh[s][2], qh[s][3], bh[2 * t], bh[2 * t + 1]);
                    mma_bf16(sc[j][0], sc[j][1], sc[j][2], sc[j][3],
                             qh[s][0], qh[s][1], qh[s][2], qh[s][3], bl[2 * t], bl[2 * t + 1]);
                    mma_bf16(sc[j][0], sc[j][1], sc[j][2], sc[j][3],
                             ql[s][0], ql[s][1], ql[s][2], ql[s][3], bh[2 * t], bh[2 * t + 1]);
                }
            }
        }

        float rmax0 = -1e30f, rmax1 = -1e30f;
#pragma unroll
        for (int j = 0; j < 8; j++) {
            const float mv0 = sMask[j * 8 + c2];
            const float mv1 = sMask[j * 8 + c2 + 1];
            sc[j][0] = sc[j][0] * 0.125f + mv0;
            sc[j][1] = sc[j][1] * 0.125f + mv1;
            sc[j][2] = sc[j][2] * 0.125f + mv0;
            sc[j][3] = sc[j][3] * 0.125f + mv1;
            rmax0 = fmaxf(rmax0, fmaxf(sc[j][0], sc[j][1]));
            rmax1 = fmaxf(rmax1, fmaxf(sc[j][2], sc[j][3]));
        }
#pragma unroll
        for (int off = 1; off <= 2; off <<= 1) {
            rmax0 = fmaxf(rmax0, __shfl_xor_sync(0xffffffffu, rmax0, off));
            rmax1 = fmaxf(rmax1, __shfl_xor_sync(0xffffffffu, rmax1, off));
        }
        const float nm0 = fmaxf(m0, rmax0);
        const float nm1 = fmaxf(m1, rmax1);
        const float a0 = __expf(m0 - nm0);
        const float a1 = __expf(m1 - nm1);

        float rs0 = 0.0f, rs1 = 0.0f;
#pragma unroll
        for (int j = 0; j < 8; j++) {
            sc[j][0] = __expf(sc[j][0] - nm0);
            sc[j][1] = __expf(sc[j][1] - nm0);
            sc[j][2] = __expf(sc[j][2] - nm1);
            sc[j][3] = __expf(sc[j][3] - nm1);
            rs0 += sc[j][0] + sc[j][1];
            rs1 += sc[j][2] + sc[j][3];
        }
#pragma unroll
        for (int off = 1; off <= 2; off <<= 1) {
            rs0 += __shfl_xor_sync(0xffffffffu, rs0, off);
            rs1 += __shfl_xor_sync(0xffffffffu, rs1, off);
        }
        l0 = l0 * a0 + rs0;
        l1 = l1 * a1 + rs1;
        m0 = nm0;
        m1 = nm1;
#pragma unroll
        for (int j = 0; j < 8; j++) {
            o[j][0] *= a0; o[j][1] *= a0;
            o[j][2] *= a1; o[j][3] *= a1;
        }

        uint32_t ph[4][4], pl[4][4];
#pragma unroll
        for (int s = 0; s < 4; s++) {
            pack_split(sc[2 * s][0],     sc[2 * s][1],     ph[s][0], pl[s][0]);
            pack_split(sc[2 * s][2],     sc[2 * s][3],     ph[s][1], pl[s][1]);
            pack_split(sc[2 * s + 1][0], sc[2 * s + 1][1], ph[s][2], pl[s][2]);
            pack_split(sc[2 * s + 1][2], sc[2 * s + 1][3], ph[s][3], pl[s][3]);
        }

#pragma unroll
        for (int s = 0; s < 4; s++) {
#pragma unroll
            for (int p = 0; p < 4; p++) {
                uint32_t bh[4], bl[4];
                ldsm_x4(bh[0], bh[1], bh[2], bh[3], sbVh + offKV[p] + s * 32);
                ldsm_x4(bl[0], bl[1], bl[2], bl[3], sbVl + offKV[p] + s * 32);
#pragma unroll
                for (int t = 0; t < 2; t++) {
                    const int j = 2 * p + t;
                    mma_bf16(o[j][0], o[j][1], o[j][2], o[j][3],
                             ph[s][0], ph[s][1], ph[s][2], ph[s][3], bh[2 * t], bh[2 * t + 1]);
                    mma_bf16(o[j][0], o[j][1], o[j][2], o[j][3],
                             ph[s][0], ph[s][1], ph[s][2], ph[s][3], bl[2 * t], bl[2 * t + 1]);
                    mma_bf16(o[j][0], o[j][1], o[j][2], o[j][3],
                             pl[s][0], pl[s][1], pl[s][2], pl[s][3], bh[2 * t], bh[2 * t + 1]);
                }
            }
        }
    }

    const float inv0 = 1.0f / l0;
    const float inv1 = 1.0f / l1;
    const size_t r0 = row_base + q0 + wid * 16 + g;
    const size_t r1 = r0 + 8;
#pragma unroll
    for (int j = 0; j < 8; j++) {
        uint32_t h0, lo0, h1, lo1;
        pack_split(o[j][0] * inv0, o[j][1] * inv0, h0, lo0);
        pack_split(o[j][2] * inv1, o[j][3] * inv1, h1, lo1);
        const size_t o0 = r0 * HID + hoff + j * 8 + c2;
        const size_t o1 = r1 * HID + hoff + j * 8 + c2;
        *(uint32_t*)(ctxh + o0) = h0;
        *(uint32_t*)(ctxl + o0) = lo0;
        *(uint32_t*)(ctxh + o1) = h1;
        *(uint32_t*)(ctxl + o1) = lo1;
    }
}

// ---------------------------------------------------------------------------
extern "C" void kernel_launch(void* const* d_in, const int* in_sizes, int n_in,
                              void* d_out, int out_size)
{
    const float* hidden = (const float*)d_in[0];
    const float* mask   = (const float*)d_in[1];
    const float* w_attn = (const float*)d_in[2];
    const float* b_attn = (const float*)d_in[3];
    const float* w_proj = (const float*)d_in[4];
    const float* b_proj = (const float*)d_in[5];
    float* out = (float*)d_out;

    __nv_bfloat16 *hh, *hl, *qkvh, *qkvl, *ctxh, *ctxl, *vTh, *vTl, *wTh, *wTl, *pTh, *pTl;
    cudaGetSymbolAddress((void**)&hh,   g_hh);
    cudaGetSymbolAddress((void**)&hl,   g_hl);
    cudaGetSymbolAddress((void**)&qkvh, g_qkvh);
    cudaGetSymbolAddress((void**)&qkvl, g_qkvl);
    cudaGetSymbolAddress((void**)&ctxh, g_ctxh);
    cudaGetSymbolAddress((void**)&ctxl, g_ctxl);
    cudaGetSymbolAddress((void**)&vTh,  g_vTh);
    cudaGetSymbolAddress((void**)&vTl,  g_vTl);
    cudaGetSymbolAddress((void**)&wTh,  g_wTh);
    cudaGetSymbolAddress((void**)&wTl,  g_wTl);
    cudaGetSymbolAddress((void**)&pTh,  g_pTh);
    cudaGetSymbolAddress((void**)&pTl,  g_pTl);

    static bool attr_set = false;
    if (!attr_set) {
        cudaFuncSetAttribute(flash_attn_tc,
                             cudaFuncAttributeMaxDynamicSharedMemorySize, SMEM_TOT);
        cudaFuncSetAttribute(gemm_bf16_pipe,
                             cudaFuncAttributeMaxDynamicSharedMemorySize, G_SMEM);
        attr_set = true;
    }

    // 0) Fused prep: weight transposes + activation split, one launch
    prep_all<<<8192, 256>>>(hidden, w_attn, w_proj, hh, hl, wTh, wTl, pTh, pTl);

    // 1) QKV GEMM -> split-bf16 qkv (Q/K) + transposed split V -> vT (fused)
    gemm_bf16_pipe<<<dim3(QKV_N / 128, M_TOT / 128), 256, G_SMEM>>>(
        hh, hl, wTh, wTl, b_attn, nullptr, qkvh, qkvl, vTh, vTl, HID, QKV_N);

    // 2) Flash attention (256 q-rows per CTA, 3-stage pipeline) -> split-bf16 ctx
    flash_attn_tc<<<dim3(SEQ / 256, NHEAD, BATCH), 512, SMEM_TOT>>>(
        qkvh, qkvl, vTh, vTl, mask, ctxh, ctxl);

    // 3) out = ctx @ c_proj_w + b
    gemm_bf16_pipe<<<dim3(HID / 128, M_TOT / 128), 256, G_SMEM>>>(
        ctxh, ctxl, pTh, pTl, b_proj, out, nullptr, nullptr, nullptr, nullptr, HID, HID);
}

// round 13
// speedup vs baseline: 1.0540x; 1.0540x over previous
#include <cuda_runtime.h>
#include <cuda_bf16.h>
#include <cstdint>

// Problem constants
#define BATCH   2
#define SEQ     2048
#define HID     1024
#define NHEAD   16
#define HDIM    64
#define QKV_N   (3 * HID)     // 3072
#define M_TOT   (BATCH * SEQ) // 4096

// Scratch (device globals: allocation-free rule)
__device__ __nv_bfloat16 g_hh[(size_t)M_TOT * HID];
__device__ __nv_bfloat16 g_hl[(size_t)M_TOT * HID];
__device__ __nv_bfloat16 g_qkvh[(size_t)M_TOT * QKV_N];
__device__ __nv_bfloat16 g_qkvl[(size_t)M_TOT * QKV_N];
__device__ __nv_bfloat16 g_ctxh[(size_t)M_TOT * HID];
__device__ __nv_bfloat16 g_ctxl[(size_t)M_TOT * HID];
__device__ __nv_bfloat16 g_vTh[(size_t)BATCH * HID * SEQ];
__device__ __nv_bfloat16 g_vTl[(size_t)BATCH * HID * SEQ];
__device__ __nv_bfloat16 g_wTh[(size_t)QKV_N * HID];
__device__ __nv_bfloat16 g_wTl[(size_t)QKV_N * HID];
__device__ __nv_bfloat16 g_pTh[(size_t)HID * HID];
__device__ __nv_bfloat16 g_pTl[(size_t)HID * HID];

// ---------------------------------------------------------------------------
// Helpers
// ---------------------------------------------------------------------------
__device__ __forceinline__ void split_bf16(float a, __nv_bfloat16& h, __nv_bfloat16& l) {
    h = __float2bfloat16_rn(a);
    l = __float2bfloat16_rn(a - __bfloat162float(h));
}

__device__ __forceinline__ void pack_split(float x, float y, uint32_t& hi, uint32_t& lo) {
    __nv_bfloat16 hx, lx, hy, ly;
    split_bf16(x, hx, lx);
    split_bf16(y, hy, ly);
    __nv_bfloat162 ph = {hx, hy}, pl = {lx, ly};
    hi = *(uint32_t*)&ph;
    lo = *(uint32_t*)&pl;
}

__device__ __forceinline__ void mma_bf16(
    float& d0, float& d1, float& d2, float& d3,
    uint32_t a0, uint32_t a1, uint32_t a2, uint32_t a3,
    uint32_t b0, uint32_t b1)
{
    asm volatile(
        "mma.sync.aligned.m16n8k16.row.col.f32.bf16.bf16.f32 "
        "{%0,%1,%2,%3}, {%4,%5,%6,%7}, {%8,%9}, {%0,%1,%2,%3};"
        : "+f"(d0), "+f"(d1), "+f"(d2), "+f"(d3)
        : "r"(a0), "r"(a1), "r"(a2), "r"(a3), "r"(b0), "r"(b1));
}

__device__ __forceinline__ void ldsm_x4(uint32_t& r0, uint32_t& r1, uint32_t& r2, uint32_t& r3,
                                        uint32_t addr)
{
    asm volatile("ldmatrix.sync.aligned.m8n8.x4.shared.b16 {%0,%1,%2,%3}, [%4];"
                 : "=r"(r0), "=r"(r1), "=r"(r2), "=r"(r3) : "r"(addr));
}

__device__ __forceinline__ uint32_t smem_u32(const void* p) {
    uint32_t a;
    asm("{ .reg .u64 t; cvta.to.shared.u64 t, %1; cvt.u32.u64 %0, t; }"
        : "=r"(a) : "l"(p));
    return a;
}

__device__ __forceinline__ void cp_async16(uint32_t dst, const void* src) {
    asm volatile("cp.async.ca.shared.global [%0], [%1], 16;" :: "r"(dst), "l"(src));
}
#define CP_COMMIT() asm volatile("cp.async.commit_group;" ::: "memory")
#define CP_WAIT(n)  asm volatile("cp.async.wait_group %0;" :: "n"(n) : "memory")

// ---------------------------------------------------------------------------
// Fused prep: both weight transposes + activation split, one launch.
// blocks [0, 3072): w_attn transpose; [3072, 4096): w_proj transpose;
// [4096, 8192): hidden split. 256 threads each.
// ---------------------------------------------------------------------------
__global__ __launch_bounds__(256) void prep_all(
    const float* __restrict__ hidden,
    const float* __restrict__ w_attn, const float* __restrict__ w_proj,
    __nv_bfloat16* __restrict__ hh,  __nv_bfloat16* __restrict__ hl,
    __nv_bfloat16* __restrict__ wTh, __nv_bfloat16* __restrict__ wTl,
    __nv_bfloat16* __restrict__ pTh, __nv_bfloat16* __restrict__ pTl)
{
    const int bid = blockIdx.x;
    const int tid = threadIdx.x;

    if (bid < 4096) {
        __shared__ float t[32][33];
        const float* B;
        __nv_bfloat16 *Bh, *Bl;
        int n0, k0, N, K;
        if (bid < 3072) {
            B = w_attn; Bh = wTh; Bl = wTl; N = QKV_N; K = HID;
            n0 = (bid % 96) * 32; k0 = (bid / 96) * 32;
        } else {
            const int b2 = bid - 3072;
            B = w_proj; Bh = pTh; Bl = pTl; N = HID; K = HID;
            n0 = (b2 % 32) * 32; k0 = (b2 / 32) * 32;
        }
        const int x = tid & 31, y = tid >> 5; // (32, 8)
#pragma unroll
        for (int i = y; i < 32; i += 8)
            t[i][x] = B[(size_t)(k0 + i) * N + n0 + x];
        __syncthreads();
#pragma unroll
        for (int i = y; i < 32; i += 8) {
            float a = t[x][i];
            __nv_bfloat16 h, l;
            split_bf16(a, h, l);
            Bh[(size_t)(n0 + i) * K + k0 + x] = h;
            Bl[(size_t)(n0 + i) * K + k0 + x] = l;
        }
    } else {
        const size_t i = ((size_t)(bid - 4096) * 256 + tid) * 4;
        float4 v = *(const float4*)(hidden + i);
        uint32_t h0, l0, h1, l1;
        pack_split(v.x, v.y, h0, l0);
        pack_split(v.z, v.w, h1, l1);
        uint2 ph = {h0, h1}, pl = {l0, l1};
        *(uint2*)(hh + i) = ph;
        *(uint2*)(hl + i) = pl;
    }
}

// ---------------------------------------------------------------------------
// All-bf16 cp.async GEMM with ldmatrix fragments (round-8 proven ordering).
// V-region tiles (n0 >= 2*HID when Ch!=null) written transposed to vT.
// ---------------------------------------------------------------------------
#define G_AH 0
#define G_AL 10240
#define G_BH 20480
#define G_BL 30720
#define G_STAGE 40960
#define G_SMEM (2 * G_STAGE)

__global__ __launch_bounds__(256, 2) void gemm_bf16_pipe(
    const __nv_bfloat16* __restrict__ Ah, const __nv_bfloat16* __restrict__ Al,
    const __nv_bfloat16* __restrict__ Bth, const __nv_bfloat16* __restrict__ Btl,
    const float* __restrict__ bias, float* __restrict__ C,
    __nv_bfloat16* __restrict__ Ch, __nv_bfloat16* __restrict__ Cl,
    __nv_bfloat16* __restrict__ VTh, __nv_bfloat16* __restrict__ VTl,
    int K, int N)
{
    extern __shared__ char smem[];
    const uint32_t smem_base = smem_u32(smem);

    const int tid = threadIdx.x;
    const int wid = tid >> 5;
    const int lane = tid & 31;
    const int g  = lane >> 2;
    const int c2 = (lane & 3) * 2;
    const int warp_m = wid & 1;
    const int warp_n = wid >> 1;
    const int m0 = blockIdx.y * 128;
    const int n0 = blockIdx.x * 128;
    const int wm = warp_m * 64;
    const int wn = warp_n * 32;

    const int lrA = lane & 15;
    const int lcA = (lane >> 4) * 8;
    uint32_t offA[4];
#pragma unroll
    for (int mi = 0; mi < 4; mi++)
        offA[mi] = (uint32_t)(((wm + mi * 16 + lrA) * 40 + lcA) * 2);
    uint32_t offB[2];
#pragma unroll
    for (int p = 0; p < 2; p++)
        offB[p] = (uint32_t)(((wn + p * 16 + ((lane >> 4) & 1) * 8 + (lane & 7)) * 40
                              + ((lane >> 3) & 1) * 8) * 2);

    float acc[4][4][4];
#pragma unroll
    for (int mi = 0; mi < 4; mi++)
#pragma unroll
        for (int ni = 0; ni < 4; ni++)
#pragma unroll
            for (int r = 0; r < 4; r++) acc[mi][ni][r] = 0.0f;

    auto issue = [&](int k0, int st) {
        const uint32_t sb = smem_base + st * G_STAGE;
#pragma unroll
        for (int it = 0; it < 2; it++) {
            const int idx = tid + it * 256;
            const int r = idx >> 2;
            const int q = idx & 3;
            const size_t aoff = (size_t)(m0 + r) * K + k0 + q * 8;
            const size_t boff = (size_t)(n0 + r) * K + k0 + q * 8;
            const uint32_t d = r * 80 + q * 16;
            cp_async16(sb + G_AH + d, Ah + aoff);
            cp_async16(sb + G_AL + d, Al + aoff);
            cp_async16(sb + G_BH + d, Bth + boff);
            cp_async16(sb + G_BL + d, Btl + boff);
        }
        CP_COMMIT();
    };

    const int nchunks = K >> 5;
    issue(0, 0);

    for (int ic = 0; ic < nchunks; ic++) {
        const int st = ic & 1;
        CP_WAIT(0);
        __syncthreads();
        if (ic + 1 < nchunks) issue((ic + 1) << 5, st ^ 1);

        const uint32_t sb = smem_base + st * G_STAGE;

#pragma unroll
        for (int kk = 0; kk < 32; kk += 16) {
            uint32_t ah[4][4], al[4][4];
#pragma unroll
            for (int mi = 0; mi < 4; mi++) {
                ldsm_x4(ah[mi][0], ah[mi][1], ah[mi][2], ah[mi][3],
                        sb + G_AH + offA[mi] + kk * 2);
                ldsm_x4(al[mi][0], al[mi][1], al[mi][2], al[mi][3],
                        sb + G_AL + offA[mi] + kk * 2);
            }
#pragma unroll
            for (int p = 0; p < 2; p++) {
                uint32_t bh[4], bl[4];
                ldsm_x4(bh[0], bh[1], bh[2], bh[3], sb + G_BH + offB[p] + kk * 2);
                ldsm_x4(bl[0], bl[1], bl[2], bl[3], sb + G_BL + offB[p] + kk * 2);
#pragma unroll
                for (int t = 0; t < 2; t++) {
                    const int ni = 2 * p + t;
                    const uint32_t bh0 = bh[2 * t], bh1 = bh[2 * t + 1];
                    const uint32_t bl0 = bl[2 * t], bl1 = bl[2 * t + 1];
#pragma unroll
                    for (int mi = 0; mi < 4; mi++) {
                        mma_bf16(acc[mi][ni][0], acc[mi][ni][1], acc[mi][ni][2], acc[mi][ni][3],
                                 ah[mi][0], ah[mi][1], ah[mi][2], ah[mi][3], bh0, bh1);
                        mma_bf16(acc[mi][ni][0], acc[mi][ni][1], acc[mi][ni][2], acc[mi][ni][3],
                                 ah[mi][0], ah[mi][1], ah[mi][2], ah[mi][3], bl0, bl1);
                        mma_bf16(acc[mi][ni][0], acc[mi][ni][1], acc[mi][ni][2], acc[mi][ni][3],
                                 al[mi][0], al[mi][1], al[mi][2], al[mi][3], bh0, bh1);
                    }
                }
            }
        }
    }

    if (Ch) {
        if (n0 >= 2 * HID) {
            // ---- V-region tile: transpose through SMEM, write vT [b][d][s] ----
            __syncthreads();
            __nv_bfloat16* sH = (__nv_bfloat16*)smem;              // [128][136]
            __nv_bfloat16* sL = (__nv_bfloat16*)(smem + 34816);    // [128][136]
#pragma unroll
            for (int mi = 0; mi < 4; mi++) {
                const int r0 = wm + mi * 16 + g;
#pragma unroll
                for (int ni = 0; ni < 4; ni++) {
                    const int colL = wn + ni * 8 + c2;
                    const float b0 = __ldg(bias + n0 + colL);
                    const float b1 = __ldg(bias + n0 + colL + 1);
                    __nv_bfloat16 h, l;
                    float v;
                    v = acc[mi][ni][0] + b0; split_bf16(v, h, l);
                    sH[colL * 136 + r0] = h;           sL[colL * 136 + r0] = l;
                    v = acc[mi][ni][1] + b1; split_bf16(v, h, l);
                    sH[(colL + 1) * 136 + r0] = h;     sL[(colL + 1) * 136 + r0] = l;
                    v = acc[mi][ni][2] + b0; split_bf16(v, h, l);
                    sH[colL * 136 + r0 + 8] = h;       sL[colL * 136 + r0 + 8] = l;
                    v = acc[mi][ni][3] + b1; split_bf16(v, h, l);
                    sH[(colL + 1) * 136 + r0 + 8] = h; sL[(colL + 1) * 136 + r0 + 8] = l;
                }
            }
            __syncthreads();
            const int bidx  = m0 >> 11;
            const int s0    = m0 & (SEQ - 1);
            const int dbase = n0 - 2 * HID;
#pragma unroll
            for (int it = 0; it < 8; it++) {
                const int idx = tid + it * 256;
                const int d  = idx >> 4;
                const int ch = idx & 15;
                uint4 vh = *(const uint4*)(sH + d * 136 + ch * 8);
                uint4 vl = *(const uint4*)(sL + d * 136 + ch * 8);
                const size_t dst = ((size_t)bidx * HID + dbase + d) * SEQ + s0 + ch * 8;
                *(uint4*)(VTh + dst) = vh;
                *(uint4*)(VTl + dst) = vl;
            }
        } else {
#pragma unroll
            for (int mi = 0; mi < 4; mi++) {
                const int row0 = m0 + wm + mi * 16 + g;
#pragma unroll
                for (int ni = 0; ni < 4; ni++) {
                    const int colL = wn + ni * 8 + c2;
                    const float b0 = __ldg(bias + n0 + colL);
                    const float b1 = __ldg(bias + n0 + colL + 1);
                    uint32_t h0, l0, h1, l1;
                    pack_split(acc[mi][ni][0] + b0, acc[mi][ni][1] + b1, h0, l0);
                    pack_split(acc[mi][ni][2] + b0, acc[mi][ni][3] + b1, h1, l1);
                    const size_t o0 = (size_t)row0 * N + n0 + colL;
                    const size_t o1 = (size_t)(row0 + 8) * N + n0 + colL;
                    *(uint32_t*)(Ch + o0) = h0;
                    *(uint32_t*)(Cl + o0) = l0;
                    *(uint32_t*)(Ch + o1) = h1;
                    *(uint32_t*)(Cl + o1) = l1;
                }
            }
        }
    } else {
#pragma unroll
        for (int mi = 0; mi < 4; mi++) {
            const int row0 = m0 + wm + mi * 16 + g;
#pragma unroll
            for (int ni = 0; ni < 4; ni++) {
                const int colL = wn + ni * 8 + c2;
                const float b0 = __ldg(bias + n0 + colL);
                const float b1 = __ldg(bias + n0 + colL + 1);
                float2 v0 = {acc[mi][ni][0] + b0, acc[mi][ni][1] + b1};
                float2 v1 = {acc[mi][ni][2] + b0, acc[mi][ni][3] + b1};
                *(float2*)(C + (size_t)row0 * N + n0 + colL) = v0;
                *(float2*)(C + (size_t)(row0 + 8) * N + n0 + colL) = v1;
            }
        }
    }
}

// ===========================================================================
// Flash attention (round-11 proven): 256 q-rows per CTA, 512 threads,
// 2-stage cp.async pipeline, per-tile mask loads.
// ===========================================================================
#define KH_OFF   0
#define KL_OFF   9216
#define VH_OFF   18432
#define VL_OFF   27648
#define STAGE_SZ 36864
#define MASK_OFF 73728
#define SMEM_TOT 74240

__global__ __launch_bounds__(512, 1) void flash_attn_tc(
    const __nv_bfloat16* __restrict__ qkvh, const __nv_bfloat16* __restrict__ qkvl,
    const __nv_bfloat16* __restrict__ vTh,  const __nv_bfloat16* __restrict__ vTl,
    const float* __restrict__ mask,
    __nv_bfloat16* __restrict__ ctxh, __nv_bfloat16* __restrict__ ctxl)
{
    extern __shared__ char smem[];
    const uint32_t smem_base = smem_u32(smem);

    const int tid  = threadIdx.x;
    const int wid  = tid >> 5;          // 0..15
    const int lane = tid & 31;
    const int g    = lane >> 2;
    const int c2   = (lane & 3) * 2;
    const int q0   = blockIdx.x * 256;
    const int h    = blockIdx.y;
    const int b    = blockIdx.z;

    const size_t row_base = (size_t)b * SEQ;
    const int hoff  = h * HDIM;
    const int khoff = HID + hoff;
    const size_t vrow_base = ((size_t)b * HID + hoff) * SEQ;

    uint32_t offKV[4];
#pragma unroll
    for (int p = 0; p < 4; p++)
        offKV[p] = (uint32_t)(((p * 16 + ((lane >> 4) & 1) * 8 + (lane & 7)) * 72
                               + ((lane >> 3) & 1) * 8) * 2);

    uint32_t qh[4][4], ql[4][4];
    {
        const __nv_bfloat16* qr0 = qkvh + (row_base + q0 + wid * 16 + g) * QKV_N + hoff;
        const __nv_bfloat16* qr1 = qr0 + 8 * QKV_N;
        const __nv_bfloat16* lr0 = qkvl + (row_base + q0 + wid * 16 + g) * QKV_N + hoff;
        const __nv_bfloat16* lr1 = lr0 + 8 * QKV_N;
#pragma unroll
        for (int s = 0; s < 4; s++) {
            qh[s][0] = *(const uint32_t*)(qr0 + s * 16 + c2);
            qh[s][1] = *(const uint32_t*)(qr1 + s * 16 + c2);
            qh[s][2] = *(const uint32_t*)(qr0 + s * 16 + 8 + c2);
            qh[s][3] = *(const uint32_t*)(qr1 + s * 16 + 8 + c2);
            ql[s][0] = *(const uint32_t*)(lr0 + s * 16 + c2);
            ql[s][1] = *(const uint32_t*)(lr1 + s * 16 + c2);
            ql[s][2] = *(const uint32_t*)(lr0 + s * 16 + 8 + c2);
            ql[s][3] = *(const uint32_t*)(lr1 + s * 16 + 8 + c2);
        }
    }

    float o[8][4];
#pragma unroll
    for (int j = 0; j < 8; j++)
#pragma unroll
        for (int r = 0; r < 4; r++) o[j][r] = 0.0f;
    float m0 = -1e30f, m1 = -1e30f, l0 = 0.0f, l1 = 0.0f;

    auto issue_tile = [&](int k0, int st) {
        const uint32_t sb = smem_base + st * STAGE_SZ;
#pragma unroll
        for (int it = 0; it < 2; it++) {
            const int idx = tid + it * 512;
            const int bufsel = idx >> 9;
            const int j = idx & 511;
            const int r = j >> 3;
            const int q = j & 7;
            const __nv_bfloat16* src =
                (bufsel ? qkvl : qkvh) + (row_base + k0 + r) * QKV_N + khoff + q * 8;
            cp_async16(sb + (bufsel ? KL_OFF : KH_OFF) + r * 144 + q * 16, src);
        }
#pragma unroll
        for (int it = 0; it < 2; it++) {
            const int idx = tid + it * 512;
            const int bufsel = idx >> 9;
            const int j = idx & 511;
            const int r = j >> 3;
            const int q = j & 7;
            const __nv_bfloat16* src =
                (bufsel ? vTl : vTh) + vrow_base + (size_t)r * SEQ + k0 + q * 8;
            cp_async16(sb + (bufsel ? VL_OFF : VH_OFF) + r * 144 + q * 16, src);
        }
        if (tid < 64)
            *(float*)(smem + MASK_OFF + st * 256 + tid * 4) = mask[(size_t)b * SEQ + k0 + tid];
        CP_COMMIT();
    };

    issue_tile(0, 0);

    for (int i = 0; i < SEQ / 64; i++) {
        const int st = i & 1;
        CP_WAIT(0);
        __syncthreads();
        if (i + 1 < SEQ / 64) issue_tile((i + 1) * 64, st ^ 1);

        const uint32_t sbKh = smem_base + st * STAGE_SZ + KH_OFF;
        const uint32_t sbKl = smem_base + st * STAGE_SZ + KL_OFF;
        const uint32_t sbVh = smem_base + st * STAGE_SZ + VH_OFF;
        const uint32_t sbVl = smem_base + st * STAGE_SZ + VL_OFF;
        const float* sMask = (const float*)(smem + MASK_OFF + st * 256);

        float sc[8][4];
#pragma unroll
        for (int j = 0; j < 8; j++)
#pragma unroll
            for (int r = 0; r < 4; r++) sc[j][r] = 0.0f;

#pragma unroll
        for (int s = 0; s < 4; s++) {
#pragma unroll
            for (int p = 0; p < 4; p++) {
                uint32_t bh[4], bl[4];
                ldsm_x4(bh[0], bh[1], bh[2], bh[3], sbKh + offKV[p] + s * 32);
                ldsm_x4(bl[0], bl[1], bl[2], bl[3], sbKl + offKV[p] + s * 32);
#pragma unroll
                for (int t = 0; t < 2; t++) {
                    const int j = 2 * p + t;
                    mma_bf16(sc[j][0], sc[j][1], sc[j][2], sc[j][3],
                             qh[s][0], qh[s][1], qh[s][2], qh[s][3], bh[2 * t], bh[2 * t + 1]);
                    mma_bf16(sc[j][0], sc[j][1], sc[j][2], sc[j][3],
                             qh[s][0], qh[s][1], qh[s][2], qh[s][3], bl[2 * t], bl[2 * t + 1]);
                    mma_bf16(sc[j][0], sc[j][1], sc[j][2], sc[j][3],
                             ql[s][0], ql[s][1], ql[s][2], ql[s][3], bh[2 * t], bh[2 * t + 1]);
                }
            }
        }

        float rmax0 = -1e30f, rmax1 = -1e30f;
#pragma unroll
        for (int j = 0; j < 8; j++) {
            const float mv0 = sMask[j * 8 + c2];
            const float mv1 = sMask[j * 8 + c2 + 1];
            sc[j][0] = sc[j][0] * 0.125f + mv0;
            sc[j][1] = sc[j][1] * 0.125f + mv1;
            sc[j][2] = sc[j][2] * 0.125f + mv0;
            sc[j][3] = sc[j][3] * 0.125f + mv1;
            rmax0 = fmaxf(rmax0, fmaxf(sc[j][0], sc[j][1]));
            rmax1 = fmaxf(rmax1, fmaxf(sc[j][2], sc[j][3]));
        }
#pragma unroll
        for (int off = 1; off <= 2; off <<= 1) {
            rmax0 = fmaxf(rmax0, __shfl_xor_sync(0xffffffffu, rmax0, off));
            rmax1 = fmaxf(rmax1, __shfl_xor_sync(0xffffffffu, rmax1, off));
        }
        const float nm0 = fmaxf(m0, rmax0);
        const float nm1 = fmaxf(m1, rmax1);
        const float a0 = __expf(m0 - nm0);
        const float a1 = __expf(m1 - nm1);

        float rs0 = 0.0f, rs1 = 0.0f;
#pragma unroll
        for (int j = 0; j < 8; j++) {
            sc[j][0] = __expf(sc[j][0] - nm0);
            sc[j][1] = __expf(sc[j][1] - nm0);
            sc[j][2] = __expf(sc[j][2] - nm1);
            sc[j][3] = __expf(sc[j][3] - nm1);
            rs0 += sc[j][0] + sc[j][1];
            rs1 += sc[j][2] + sc[j][3];
        }
#pragma unroll
        for (int off = 1; off <= 2; off <<= 1) {
            rs0 += __shfl_xor_sync(0xffffffffu, rs0, off);
            rs1 += __shfl_xor_sync(0xffffffffu, rs1, off);
        }
        l0 = l0 * a0 + rs0;
        l1 = l1 * a1 + rs1;
        m0 = nm0;
        m1 = nm1;
#pragma unroll
        for (int j = 0; j < 8; j++) {
            o[j][0] *= a0; o[j][1] *= a0;
            o[j][2] *= a1; o[j][3] *= a1;
        }

        uint32_t ph[4][4], pl[4][4];
#pragma unroll
        for (int s = 0; s < 4; s++) {
            pack_split(sc[2 * s][0],     sc[2 * s][1],     ph[s][0], pl[s][0]);
            pack_split(sc[2 * s][2],     sc[2 * s][3],     ph[s][1], pl[s][1]);
            pack_split(sc[2 * s + 1][0], sc[2 * s + 1][1], ph[s][2], pl[s][2]);
            pack_split(sc[2 * s + 1][2], sc[2 * s + 1][3], ph[s][3], pl[s][3]);
        }

#pragma unroll
        for (int s = 0; s < 4; s++) {
#pragma unroll
            for (int p = 0; p < 4; p++) {
                uint32_t bh[4], bl[4];
                ldsm_x4(bh[0], bh[1], bh[2], bh[3], sbVh + offKV[p] + s * 32);
                ldsm_x4(bl[0], bl[1], bl[2], bl[3], sbVl + offKV[p] + s * 32);
#pragma unroll
                for (int t = 0; t < 2; t++) {
                    const int j = 2 * p + t;
                    mma_bf16(o[j][0], o[j][1], o[j][2], o[j][3],
                             ph[s][0], ph[s][1], ph[s][2], ph[s][3], bh[2 * t], bh[2 * t + 1]);
                    mma_bf16(o[j][0], o[j][1], o[j][2], o[j][3],
                             ph[s][0], ph[s][1], ph[s][2], ph[s][3], bl[2 * t], bl[2 * t + 1]);
                    mma_bf16(o[j][0], o[j][1], o[j][2], o[j][3],
                             pl[s][0], pl[s][1], pl[s][2], pl[s][3], bh[2 * t], bh[2 * t + 1]);
                }
            }
        }
    }

    const float inv0 = 1.0f / l0;
    const float inv1 = 1.0f / l1;
    const size_t r0 = row_base + q0 + wid * 16 + g;
    const size_t r1 = r0 + 8;
#pragma unroll
    for (int j = 0; j < 8; j++) {
        uint32_t h0, lo0, h1, lo1;
        pack_split(o[j][0] * inv0, o[j][1] * inv0, h0, lo0);
        pack_split(o[j][2] * inv1, o[j][3] * inv1, h1, lo1);
        const size_t o0 = r0 * HID + hoff + j * 8 + c2;
        const size_t o1 = r1 * HID + hoff + j * 8 + c2;
        *(uint32_t*)(ctxh + o0) = h0;
        *(uint32_t*)(ctxl + o0) = lo0;
        *(uint32_t*)(ctxh + o1) = h1;
        *(uint32_t*)(ctxl + o1) = lo1;
    }
}

// ---------------------------------------------------------------------------
extern "C" void kernel_launch(void* const* d_in, const int* in_sizes, int n_in,
                              void* d_out, int out_size)
{
    const float* hidden = (const float*)d_in[0];
    const float* mask   = (const float*)d_in[1];
    const float* w_attn = (const float*)d_in[2];
    const float* b_attn = (const float*)d_in[3];
    const float* w_proj = (const float*)d_in[4];
    const float* b_proj = (const float*)d_in[5];
    float* out = (float*)d_out;

    __nv_bfloat16 *hh, *hl, *qkvh, *qkvl, *ctxh, *ctxl, *vTh, *vTl, *wTh, *wTl, *pTh, *pTl;
    cudaGetSymbolAddress((void**)&hh,   g_hh);
    cudaGetSymbolAddress((void**)&hl,   g_hl);
    cudaGetSymbolAddress((void**)&qkvh, g_qkvh);
    cudaGetSymbolAddress((void**)&qkvl, g_qkvl);
    cudaGetSymbolAddress((void**)&ctxh, g_ctxh);
    cudaGetSymbolAddress((void**)&ctxl, g_ctxl);
    cudaGetSymbolAddress((void**)&vTh,  g_vTh);
    cudaGetSymbolAddress((void**)&vTl,  g_vTl);
    cudaGetSymbolAddress((void**)&wTh,  g_wTh);
    cudaGetSymbolAddress((void**)&wTl,  g_wTl);
    cudaGetSymbolAddress((void**)&pTh,  g_pTh);
    cudaGetSymbolAddress((void**)&pTl,  g_pTl);

    static bool attr_set = false;
    if (!attr_set) {
        cudaFuncSetAttribute(flash_attn_tc,
                             cudaFuncAttributeMaxDynamicSharedMemorySize, SMEM_TOT);
        cudaFuncSetAttribute(gemm_bf16_pipe,
                             cudaFuncAttributeMaxDynamicSharedMemorySize, G_SMEM);
        attr_set = true;
    }

    // 0) Fused prep (single launch): weight transposes + activation split
    prep_all<<<8192, 256>>>(hidden, w_attn, w_proj, hh, hl, wTh, wTl, pTh, pTl);

    // 1) QKV GEMM -> split-bf16 qkv (Q/K) + transposed split V -> vT (fused)
    gemm_bf16_pipe<<<dim3(QKV_N / 128, M_TOT / 128), 256, G_SMEM>>>(
        hh, hl, wTh, wTl, b_attn, nullptr, qkvh, qkvl, vTh, vTl, HID, QKV_N);

    // 2) Flash attention (256 q-rows per CTA) -> split-bf16 ctx
    flash_attn_tc<<<dim3(SEQ / 256, NHEAD, BATCH), 512, SMEM_TOT>>>(
        qkvh, qkvl, vTh, vTl, mask, ctxh, ctxl);

    // 3) out = ctx @ c_proj_w + b
    gemm_bf16_pipe<<<dim3(HID / 128, M_TOT / 128), 256, G_SMEM>>>(
        ctxh, ctxl, pTh, pTl, b_proj, out, nullptr, nullptr, nullptr, nullptr, HID, HID);
}

// round 14
// speedup vs baseline: 1.0581x; 1.0039x over previous
#include <cuda_runtime.h>
#include <cuda_bf16.h>
#include <cstdint>

// Problem constants
#define BATCH   2
#define SEQ     2048
#define HID     1024
#define NHEAD   16
#define HDIM    64
#define QKV_N   (3 * HID)     // 3072
#define M_TOT   (BATCH * SEQ) // 4096

// Scratch (device globals: allocation-free rule)
__device__ __nv_bfloat16 g_hh[(size_t)M_TOT * HID];
__device__ __nv_bfloat16 g_hl[(size_t)M_TOT * HID];
__device__ __nv_bfloat16 g_qkvh[(size_t)M_TOT * QKV_N];
__device__ __nv_bfloat16 g_qkvl[(size_t)M_TOT * QKV_N];
__device__ __nv_bfloat16 g_ctxh[(size_t)M_TOT * HID];
__device__ __nv_bfloat16 g_ctxl[(size_t)M_TOT * HID];
__device__ __nv_bfloat16 g_vTh[(size_t)BATCH * HID * SEQ];
__device__ __nv_bfloat16 g_vTl[(size_t)BATCH * HID * SEQ];
__device__ __nv_bfloat16 g_wTh[(size_t)QKV_N * HID];
__device__ __nv_bfloat16 g_wTl[(size_t)QKV_N * HID];
__device__ __nv_bfloat16 g_pTh[(size_t)HID * HID];
__device__ __nv_bfloat16 g_pTl[(size_t)HID * HID];

// ---------------------------------------------------------------------------
// Helpers
// ---------------------------------------------------------------------------
__device__ __forceinline__ void split_bf16(float a, __nv_bfloat16& h, __nv_bfloat16& l) {
    h = __float2bfloat16_rn(a);
    l = __float2bfloat16_rn(a - __bfloat162float(h));
}

__device__ __forceinline__ void pack_split(float x, float y, uint32_t& hi, uint32_t& lo) {
    __nv_bfloat16 hx, lx, hy, ly;
    split_bf16(x, hx, lx);
    split_bf16(y, hy, ly);
    __nv_bfloat162 ph = {hx, hy}, pl = {lx, ly};
    hi = *(uint32_t*)&ph;
    lo = *(uint32_t*)&pl;
}

__device__ __forceinline__ void mma_bf16(
    float& d0, float& d1, float& d2, float& d3,
    uint32_t a0, uint32_t a1, uint32_t a2, uint32_t a3,
    uint32_t b0, uint32_t b1)
{
    asm volatile(
        "mma.sync.aligned.m16n8k16.row.col.f32.bf16.bf16.f32 "
        "{%0,%1,%2,%3}, {%4,%5,%6,%7}, {%8,%9}, {%0,%1,%2,%3};"
        : "+f"(d0), "+f"(d1), "+f"(d2), "+f"(d3)
        : "r"(a0), "r"(a1), "r"(a2), "r"(a3), "r"(b0), "r"(b1));
}

__device__ __forceinline__ void ldsm_x4(uint32_t& r0, uint32_t& r1, uint32_t& r2, uint32_t& r3,
                                        uint32_t addr)
{
    asm volatile("ldmatrix.sync.aligned.m8n8.x4.shared.b16 {%0,%1,%2,%3}, [%4];"
                 : "=r"(r0), "=r"(r1), "=r"(r2), "=r"(r3) : "r"(addr));
}

__device__ __forceinline__ uint32_t smem_u32(const void* p) {
    uint32_t a;
    asm("{ .reg .u64 t; cvta.to.shared.u64 t, %1; cvt.u32.u64 %0, t; }"
        : "=r"(a) : "l"(p));
    return a;
}

__device__ __forceinline__ void cp_async16(uint32_t dst, const void* src) {
    asm volatile("cp.async.ca.shared.global [%0], [%1], 16;" :: "r"(dst), "l"(src));
}
#define CP_COMMIT() asm volatile("cp.async.commit_group;" ::: "memory")
#define CP_WAIT(n)  asm volatile("cp.async.wait_group %0;" :: "n"(n) : "memory")

// ---------------------------------------------------------------------------
// Fused prep (round-13 proven): weight transposes + activation split.
// ---------------------------------------------------------------------------
__global__ __launch_bounds__(256) void prep_all(
    const float* __restrict__ hidden,
    const float* __restrict__ w_attn, const float* __restrict__ w_proj,
    __nv_bfloat16* __restrict__ hh,  __nv_bfloat16* __restrict__ hl,
    __nv_bfloat16* __restrict__ wTh, __nv_bfloat16* __restrict__ wTl,
    __nv_bfloat16* __restrict__ pTh, __nv_bfloat16* __restrict__ pTl)
{
    const int bid = blockIdx.x;
    const int tid = threadIdx.x;

    if (bid < 4096) {
        __shared__ float t[32][33];
        const float* B;
        __nv_bfloat16 *Bh, *Bl;
        int n0, k0, N, K;
        if (bid < 3072) {
            B = w_attn; Bh = wTh; Bl = wTl; N = QKV_N; K = HID;
            n0 = (bid % 96) * 32; k0 = (bid / 96) * 32;
        } else {
            const int b2 = bid - 3072;
            B = w_proj; Bh = pTh; Bl = pTl; N = HID; K = HID;
            n0 = (b2 % 32) * 32; k0 = (b2 / 32) * 32;
        }
        const int x = tid & 31, y = tid >> 5;
#pragma unroll
        for (int i = y; i < 32; i += 8)
            t[i][x] = B[(size_t)(k0 + i) * N + n0 + x];
        __syncthreads();
#pragma unroll
        for (int i = y; i < 32; i += 8) {
            float a = t[x][i];
            __nv_bfloat16 h, l;
            split_bf16(a, h, l);
            Bh[(size_t)(n0 + i) * K + k0 + x] = h;
            Bl[(size_t)(n0 + i) * K + k0 + x] = l;
        }
    } else {
        const size_t i = ((size_t)(bid - 4096) * 256 + tid) * 4;
        float4 v = *(const float4*)(hidden + i);
        uint32_t h0, l0, h1, l1;
        pack_split(v.x, v.y, h0, l0);
        pack_split(v.z, v.w, h1, l1);
        uint2 ph = {h0, h1}, pl = {l0, l1};
        *(uint2*)(hh + i) = ph;
        *(uint2*)(hl + i) = pl;
    }
}

// ---------------------------------------------------------------------------
// All-bf16 cp.async GEMM, ldmatrix fragments, B-fragment double-buffering:
// the next (kk,p) group's B ldmatrix issues BEFORE the current group's MMAs,
// hiding LDSM latency under tensor work. MMA order/operands unchanged.
// ---------------------------------------------------------------------------
#define G_AH 0
#define G_AL 10240
#define G_BH 20480
#define G_BL 30720
#define G_STAGE 40960
#define G_SMEM (2 * G_STAGE)

__global__ __launch_bounds__(256, 2) void gemm_bf16_pipe(
    const __nv_bfloat16* __restrict__ Ah, const __nv_bfloat16* __restrict__ Al,
    const __nv_bfloat16* __restrict__ Bth, const __nv_bfloat16* __restrict__ Btl,
    const float* __restrict__ bias, float* __restrict__ C,
    __nv_bfloat16* __restrict__ Ch, __nv_bfloat16* __restrict__ Cl,
    __nv_bfloat16* __restrict__ VTh, __nv_bfloat16* __restrict__ VTl,
    int K, int N)
{
    extern __shared__ char smem[];
    const uint32_t smem_base = smem_u32(smem);

    const int tid = threadIdx.x;
    const int wid = tid >> 5;
    const int lane = tid & 31;
    const int g  = lane >> 2;
    const int c2 = (lane & 3) * 2;
    const int warp_m = wid & 1;
    const int warp_n = wid >> 1;
    const int m0 = blockIdx.y * 128;
    const int n0 = blockIdx.x * 128;
    const int wm = warp_m * 64;
    const int wn = warp_n * 32;

    const int lrA = lane & 15;
    const int lcA = (lane >> 4) * 8;
    uint32_t offA[4];
#pragma unroll
    for (int mi = 0; mi < 4; mi++)
        offA[mi] = (uint32_t)(((wm + mi * 16 + lrA) * 40 + lcA) * 2);
    uint32_t offB[2];
#pragma unroll
    for (int p = 0; p < 2; p++)
        offB[p] = (uint32_t)(((wn + p * 16 + ((lane >> 4) & 1) * 8 + (lane & 7)) * 40
                              + ((lane >> 3) & 1) * 8) * 2);

    float acc[4][4][4];
#pragma unroll
    for (int mi = 0; mi < 4; mi++)
#pragma unroll
        for (int ni = 0; ni < 4; ni++)
#pragma unroll
            for (int r = 0; r < 4; r++) acc[mi][ni][r] = 0.0f;

    auto issue = [&](int k0, int st) {
        const uint32_t sb = smem_base + st * G_STAGE;
#pragma unroll
        for (int it = 0; it < 2; it++) {
            const int idx = tid + it * 256;
            const int r = idx >> 2;
            const int q = idx & 3;
            const size_t aoff = (size_t)(m0 + r) * K + k0 + q * 8;
            const size_t boff = (size_t)(n0 + r) * K + k0 + q * 8;
            const uint32_t d = r * 80 + q * 16;
            cp_async16(sb + G_AH + d, Ah + aoff);
            cp_async16(sb + G_AL + d, Al + aoff);
            cp_async16(sb + G_BH + d, Bth + boff);
            cp_async16(sb + G_BL + d, Btl + boff);
        }
        CP_COMMIT();
    };

    const int nchunks = K >> 5;
    issue(0, 0);

    for (int ic = 0; ic < nchunks; ic++) {
        const int st = ic & 1;
        CP_WAIT(0);
        __syncthreads();
        if (ic + 1 < nchunks) issue((ic + 1) << 5, st ^ 1);

        const uint32_t sb = smem_base + st * G_STAGE;

        // B-fragment double buffer across groups (kk0,p0)(kk0,p1)(kk16,p0)(kk16,p1)
        uint32_t bh[2][4], bl[2][4];
        ldsm_x4(bh[0][0], bh[0][1], bh[0][2], bh[0][3], sb + G_BH + offB[0]);
        ldsm_x4(bl[0][0], bl[0][1], bl[0][2], bl[0][3], sb + G_BL + offB[0]);
        int buf = 0;

#pragma unroll
        for (int kk = 0; kk < 32; kk += 16) {
            uint32_t ah[4][4], al[4][4];
#pragma unroll
            for (int mi = 0; mi < 4; mi++) {
                ldsm_x4(ah[mi][0], ah[mi][1], ah[mi][2], ah[mi][3],
                        sb + G_AH + offA[mi] + kk * 2);
                ldsm_x4(al[mi][0], al[mi][1], al[mi][2], al[mi][3],
                        sb + G_AL + offA[mi] + kk * 2);
            }
#pragma unroll
            for (int p = 0; p < 2; p++) {
                // Prefetch next B group before this group's MMAs
                if (!(kk == 16 && p == 1)) {
                    const int nkk = (p == 1) ? kk + 16 : kk;
                    const int npp = (p == 1) ? 0 : 1;
                    ldsm_x4(bh[buf ^ 1][0], bh[buf ^ 1][1], bh[buf ^ 1][2], bh[buf ^ 1][3],
                            sb + G_BH + offB[npp] + nkk * 2);
                    ldsm_x4(bl[buf ^ 1][0], bl[buf ^ 1][1], bl[buf ^ 1][2], bl[buf ^ 1][3],
                            sb + G_BL + offB[npp] + nkk * 2);
                }
#pragma unroll
                for (int t = 0; t < 2; t++) {
                    const int ni = 2 * p + t;
                    const uint32_t bh0 = bh[buf][2 * t], bh1 = bh[buf][2 * t + 1];
                    const uint32_t bl0 = bl[buf][2 * t], bl1 = bl[buf][2 * t + 1];
#pragma unroll
                    for (int mi = 0; mi < 4; mi++) {
                        mma_bf16(acc[mi][ni][0], acc[mi][ni][1], acc[mi][ni][2], acc[mi][ni][3],
                                 ah[mi][0], ah[mi][1], ah[mi][2], ah[mi][3], bh0, bh1);
                        mma_bf16(acc[mi][ni][0], acc[mi][ni][1], acc[mi][ni][2], acc[mi][ni][3],
                                 ah[mi][0], ah[mi][1], ah[mi][2], ah[mi][3], bl0, bl1);
                        mma_bf16(acc[mi][ni][0], acc[mi][ni][1], acc[mi][ni][2], acc[mi][ni][3],
                                 al[mi][0], al[mi][1], al[mi][2], al[mi][3], bh0, bh1);
                    }
                }
                buf ^= 1;
            }
        }
    }

    if (Ch) {
        if (n0 >= 2 * HID) {
            // ---- V-region tile: transpose through SMEM, write vT [b][d][s] ----
            __syncthreads();
            __nv_bfloat16* sH = (__nv_bfloat16*)smem;              // [128][136]
            __nv_bfloat16* sL = (__nv_bfloat16*)(smem + 34816);    // [128][136]
#pragma unroll
            for (int mi = 0; mi < 4; mi++) {
                const int r0 = wm + mi * 16 + g;
#pragma unroll
                for (int ni = 0; ni < 4; ni++) {
                    const int colL = wn + ni * 8 + c2;
                    const float b0 = __ldg(bias + n0 + colL);
                    const float b1 = __ldg(bias + n0 + colL + 1);
                    __nv_bfloat16 h, l;
                    float v;
                    v = acc[mi][ni][0] + b0; split_bf16(v, h, l);
                    sH[colL * 136 + r0] = h;           sL[colL * 136 + r0] = l;
                    v = acc[mi][ni][1] + b1; split_bf16(v, h, l);
                    sH[(colL + 1) * 136 + r0] = h;     sL[(colL + 1) * 136 + r0] = l;
                    v = acc[mi][ni][2] + b0; split_bf16(v, h, l);
                    sH[colL * 136 + r0 + 8] = h;       sL[colL * 136 + r0 + 8] = l;
                    v = acc[mi][ni][3] + b1; split_bf16(v, h, l);
                    sH[(colL + 1) * 136 + r0 + 8] = h; sL[(colL + 1) * 136 + r0 + 8] = l;
                }
            }
            __syncthreads();
            const int bidx  = m0 >> 11;
            const int s0    = m0 & (SEQ - 1);
            const int dbase = n0 - 2 * HID;
#pragma unroll
            for (int it = 0; it < 8; it++) {
                const int idx = tid + it * 256;
                const int d  = idx >> 4;
                const int ch = idx & 15;
                uint4 vh = *(const uint4*)(sH + d * 136 + ch * 8);
                uint4 vl = *(const uint4*)(sL + d * 136 + ch * 8);
                const size_t dst = ((size_t)bidx * HID + dbase + d) * SEQ + s0 + ch * 8;
                *(uint4*)(VTh + dst) = vh;
                *(uint4*)(VTl + dst) = vl;
            }
        } else {
#pragma unroll
            for (int mi = 0; mi < 4; mi++) {
                const int row0 = m0 + wm + mi * 16 + g;
#pragma unroll
                for (int ni = 0; ni < 4; ni++) {
                    const int colL = wn + ni * 8 + c2;
                    const float b0 = __ldg(bias + n0 + colL);
                    const float b1 = __ldg(bias + n0 + colL + 1);
                    uint32_t h0, l0, h1, l1;
                    pack_split(acc[mi][ni][0] + b0, acc[mi][ni][1] + b1, h0, l0);
                    pack_split(acc[mi][ni][2] + b0, acc[mi][ni][3] + b1, h1, l1);
                    const size_t o0 = (size_t)row0 * N + n0 + colL;
                    const size_t o1 = (size_t)(row0 + 8) * N + n0 + colL;
                    *(uint32_t*)(Ch + o0) = h0;
                    *(uint32_t*)(Cl + o0) = l0;
                    *(uint32_t*)(Ch + o1) = h1;
                    *(uint32_t*)(Cl + o1) = l1;
                }
            }
        }
    } else {
#pragma unroll
        for (int mi = 0; mi < 4; mi++) {
            const int row0 = m0 + wm + mi * 16 + g;
#pragma unroll
            for (int ni = 0; ni < 4; ni++) {
                const int colL = wn + ni * 8 + c2;
                const float b0 = __ldg(bias + n0 + colL);
                const float b1 = __ldg(bias + n0 + colL + 1);
                float2 v0 = {acc[mi][ni][0] + b0, acc[mi][ni][1] + b1};
                float2 v1 = {acc[mi][ni][2] + b0, acc[mi][ni][3] + b1};
                *(float2*)(C + (size_t)row0 * N + n0 + colL) = v0;
                *(float2*)(C + (size_t)(row0 + 8) * N + n0 + colL) = v1;
            }
        }
    }
}

// ===========================================================================
// Flash attention: 256 q-rows per CTA, 512 threads, 2-stage cp.async,
// PV phase with V-fragment double-buffering (sc regs dead there).
// ===========================================================================
#define KH_OFF   0
#define KL_OFF   9216
#define VH_OFF   18432
#define VL_OFF   27648
#define STAGE_SZ 36864
#define MASK_OFF 73728
#define SMEM_TOT 74240

__global__ __launch_bounds__(512, 1) void flash_attn_tc(
    const __nv_bfloat16* __restrict__ qkvh, const __nv_bfloat16* __restrict__ qkvl,
    const __nv_bfloat16* __restrict__ vTh,  const __nv_bfloat16* __restrict__ vTl,
    const float* __restrict__ mask,
    __nv_bfloat16* __restrict__ ctxh, __nv_bfloat16* __restrict__ ctxl)
{
    extern __shared__ char smem[];
    const uint32_t smem_base = smem_u32(smem);

    const int tid  = threadIdx.x;
    const int wid  = tid >> 5;
    const int lane = tid & 31;
    const int g    = lane >> 2;
    const int c2   = (lane & 3) * 2;
    const int q0   = blockIdx.x * 256;
    const int h    = blockIdx.y;
    const int b    = blockIdx.z;

    const size_t row_base = (size_t)b * SEQ;
    const int hoff  = h * HDIM;
    const int khoff = HID + hoff;
    const size_t vrow_base = ((size_t)b * HID + hoff) * SEQ;

    uint32_t offKV[4];
#pragma unroll
    for (int p = 0; p < 4; p++)
        offKV[p] = (uint32_t)(((p * 16 + ((lane >> 4) & 1) * 8 + (lane & 7)) * 72
                               + ((lane >> 3) & 1) * 8) * 2);

    uint32_t qh[4][4], ql[4][4];
    {
        const __nv_bfloat16* qr0 = qkvh + (row_base + q0 + wid * 16 + g) * QKV_N + hoff;
        const __nv_bfloat16* qr1 = qr0 + 8 * QKV_N;
        const __nv_bfloat16* lr0 = qkvl + (row_base + q0 + wid * 16 + g) * QKV_N + hoff;
        const __nv_bfloat16* lr1 = lr0 + 8 * QKV_N;
#pragma unroll
        for (int s = 0; s < 4; s++) {
            qh[s][0] = *(const uint32_t*)(qr0 + s * 16 + c2);
            qh[s][1] = *(const uint32_t*)(qr1 + s * 16 + c2);
            qh[s][2] = *(const uint32_t*)(qr0 + s * 16 + 8 + c2);
            qh[s][3] = *(const uint32_t*)(qr1 + s * 16 + 8 + c2);
            ql[s][0] = *(const uint32_t*)(lr0 + s * 16 + c2);
            ql[s][1] = *(const uint32_t*)(lr1 + s * 16 + c2);
            ql[s][2] = *(const uint32_t*)(lr0 + s * 16 + 8 + c2);
            ql[s][3] = *(const uint32_t*)(lr1 + s * 16 + 8 + c2);
        }
    }

    float o[8][4];
#pragma unroll
    for (int j = 0; j < 8; j++)
#pragma unroll
        for (int r = 0; r < 4; r++) o[j][r] = 0.0f;
    float m0 = -1e30f, m1 = -1e30f, l0 = 0.0f, l1 = 0.0f;

    auto issue_tile = [&](int k0, int st) {
        const uint32_t sb = smem_base + st * STAGE_SZ;
#pragma unroll
        for (int it = 0; it < 2; it++) {
            const int idx = tid + it * 512;
            const int bufsel = idx >> 9;
            const int j = idx & 511;
            const int r = j >> 3;
            const int q = j & 7;
            const __nv_bfloat16* src =
                (bufsel ? qkvl : qkvh) + (row_base + k0 + r) * QKV_N + khoff + q * 8;
            cp_async16(sb + (bufsel ? KL_OFF : KH_OFF) + r * 144 + q * 16, src);
        }
#pragma unroll
        for (int it = 0; it < 2; it++) {
            const int idx = tid + it * 512;
            const int bufsel = idx >> 9;
            const int j = idx & 511;
            const int r = j >> 3;
            const int q = j & 7;
            const __nv_bfloat16* src =
                (bufsel ? vTl : vTh) + vrow_base + (size_t)r * SEQ + k0 + q * 8;
            cp_async16(sb + (bufsel ? VL_OFF : VH_OFF) + r * 144 + q * 16, src);
        }
        if (tid < 64)
            *(float*)(smem + MASK_OFF + st * 256 + tid * 4) = mask[(size_t)b * SEQ + k0 + tid];
        CP_COMMIT();
    };

    issue_tile(0, 0);

    for (int i = 0; i < SEQ / 64; i++) {
        const int st = i & 1;
        CP_WAIT(0);
        __syncthreads();
        if (i + 1 < SEQ / 64) issue_tile((i + 1) * 64, st ^ 1);

        const uint32_t sbKh = smem_base + st * STAGE_SZ + KH_OFF;
        const uint32_t sbKl = smem_base + st * STAGE_SZ + KL_OFF;
        const uint32_t sbVh = smem_base + st * STAGE_SZ + VH_OFF;
        const uint32_t sbVl = smem_base + st * STAGE_SZ + VL_OFF;
        const float* sMask = (const float*)(smem + MASK_OFF + st * 256);

        float sc[8][4];
#pragma unroll
        for (int j = 0; j < 8; j++)
#pragma unroll
            for (int r = 0; r < 4; r++) sc[j][r] = 0.0f;

#pragma unroll
        for (int s = 0; s < 4; s++) {
#pragma unroll
            for (int p = 0; p < 4; p++) {
                uint32_t bh[4], bl[4];
                ldsm_x4(bh[0], bh[1], bh[2], bh[3], sbKh + offKV[p] + s * 32);
                ldsm_x4(bl[0], bl[1], bl[2], bl[3], sbKl + offKV[p] + s * 32);
#pragma unroll
                for (int t = 0; t < 2; t++) {
                    const int j = 2 * p + t;
                    mma_bf16(sc[j][0], sc[j][1], sc[j][2], sc[j][3],
                             qh[s][0], qh[s][1], qh[s][2], qh[s][3], bh[2 * t], bh[2 * t + 1]);
                    mma_bf16(sc[j][0], sc[j][1], sc[j][2], sc[j][3],
                             qh[s][0], qh[s][1], qh[s][2], qh[s][3], bl[2 * t], bl[2 * t + 1]);
                    mma_bf16(sc[j][0], sc[j][1], sc[j][2], sc[j][3],
                             ql[s][0], ql[s][1], ql[s][2], ql[s][3], bh[2 * t], bh[2 * t + 1]);
                }
            }
        }

        float rmax0 = -1e30f, rmax1 = -1e30f;
#pragma unroll
        for (int j = 0; j < 8; j++) {
            const float mv0 = sMask[j * 8 + c2];
            const float mv1 = sMask[j * 8 + c2 + 1];
            sc[j][0] = sc[j][0] * 0.125f + mv0;
            sc[j][1] = sc[j][1] * 0.125f + mv1;
            sc[j][2] = sc[j][2] * 0.125f + mv0;
            sc[j][3] = sc[j][3] * 0.125f + mv1;
            rmax0 = fmaxf(rmax0, fmaxf(sc[j][0], sc[j][1]));
            rmax1 = fmaxf(rmax1, fmaxf(sc[j][2], sc[j][3]));
        }
#pragma unroll
        for (int off = 1; off <= 2; off <<= 1) {
            rmax0 = fmaxf(rmax0, __shfl_xor_sync(0xffffffffu, rmax0, off));
            rmax1 = fmaxf(rmax1, __shfl_xor_sync(0xffffffffu, rmax1, off));
        }
        const float nm0 = fmaxf(m0, rmax0);
        const float nm1 = fmaxf(m1, rmax1);
        const float a0 = __expf(m0 - nm0);
        const float a1 = __expf(m1 - nm1);

        float rs0 = 0.0f, rs1 = 0.0f;
#pragma unroll
        for (int j = 0; j < 8; j++) {
            sc[j][0] = __expf(sc[j][0] - nm0);
            sc[j][1] = __expf(sc[j][1] - nm0);
            sc[j][2] = __expf(sc[j][2] - nm1);
            sc[j][3] = __expf(sc[j][3] - nm1);
            rs0 += sc[j][0] + sc[j][1];
            rs1 += sc[j][2] + sc[j][3];
        }
#pragma unroll
        for (int off = 1; off <= 2; off <<= 1) {
            rs0 += __shfl_xor_sync(0xffffffffu, rs0, off);
            rs1 += __shfl_xor_sync(0xffffffffu, rs1, off);
        }
        l0 = l0 * a0 + rs0;
        l1 = l1 * a1 + rs1;
        m0 = nm0;
        m1 = nm1;
#pragma unroll
        for (int j = 0; j < 8; j++) {
            o[j][0] *= a0; o[j][1] *= a0;
            o[j][2] *= a1; o[j][3] *= a1;
        }

        uint32_t ph[4][4], pl[4][4];
#pragma unroll
        for (int s = 0; s < 4; s++) {
            pack_split(sc[2 * s][0],     sc[2 * s][1],     ph[s][0], pl[s][0]);
            pack_split(sc[2 * s][2],     sc[2 * s][3],     ph[s][1], pl[s][1]);
            pack_split(sc[2 * s + 1][0], sc[2 * s + 1][1], ph[s][2], pl[s][2]);
            pack_split(sc[2 * s + 1][2], sc[2 * s + 1][3], ph[s][3], pl[s][3]);
        }

        // ---- O += P V with V-fragment double buffer (sc now dead) ----
        {
            uint32_t vbh[2][4], vbl[2][4];
            ldsm_x4(vbh[0][0], vbh[0][1], vbh[0][2], vbh[0][3], sbVh + offKV[0]);
            ldsm_x4(vbl[0][0], vbl[0][1], vbl[0][2], vbl[0][3], sbVl + offKV[0]);
            int buf = 0;
#pragma unroll
            for (int s = 0; s < 4; s++) {
#pragma unroll
                for (int p = 0; p < 4; p++) {
                    // Prefetch next (s,p) V frags before this group's MMAs
                    if (!(s == 3 && p == 3)) {
                        const int ns = (p == 3) ? s + 1 : s;
                        const int np = (p == 3) ? 0 : p + 1;
                        ldsm_x4(vbh[buf ^ 1][0], vbh[buf ^ 1][1], vbh[buf ^ 1][2], vbh[buf ^ 1][3],
                                sbVh + offKV[np] + ns * 32);
                        ldsm_x4(vbl[buf ^ 1][0], vbl[buf ^ 1][1], vbl[buf ^ 1][2], vbl[buf ^ 1][3],
                                sbVl + offKV[np] + ns * 32);
                    }
#pragma unroll
                    for (int t = 0; t < 2; t++) {
                        const int j = 2 * p + t;
                        mma_bf16(o[j][0], o[j][1], o[j][2], o[j][3],
                                 ph[s][0], ph[s][1], ph[s][2], ph[s][3],
                                 vbh[buf][2 * t], vbh[buf][2 * t + 1]);
                        mma_bf16(o[j][0], o[j][1], o[j][2], o[j][3],
                                 ph[s][0], ph[s][1], ph[s][2], ph[s][3],
                                 vbl[buf][2 * t], vbl[buf][2 * t + 1]);
                        mma_bf16(o[j][0], o[j][1], o[j][2], o[j][3],
                                 pl[s][0], pl[s][1], pl[s][2], pl[s][3],
                                 vbh[buf][2 * t], vbh[buf][2 * t + 1]);
                    }
                    buf ^= 1;
                }
            }
        }
    }

    const float inv0 = 1.0f / l0;
    const float inv1 = 1.0f / l1;
    const size_t r0 = row_base + q0 + wid * 16 + g;
    const size_t r1 = r0 + 8;
#pragma unroll
    for (int j = 0; j < 8; j++) {
        uint32_t h0, lo0, h1, lo1;
        pack_split(o[j][0] * inv0, o[j][1] * inv0, h0, lo0);
        pack_split(o[j][2] * inv1, o[j][3] * inv1, h1, lo1);
        const size_t o0 = r0 * HID + hoff + j * 8 + c2;
        const size_t o1 = r1 * HID + hoff + j * 8 + c2;
        *(uint32_t*)(ctxh + o0) = h0;
        *(uint32_t*)(ctxl + o0) = lo0;
        *(uint32_t*)(ctxh + o1) = h1;
        *(uint32_t*)(ctxl + o1) = lo1;
    }
}

// ---------------------------------------------------------------------------
extern "C" void kernel_launch(void* const* d_in, const int* in_sizes, int n_in,
                              void* d_out, int out_size)
{
    const float* hidden = (const float*)d_in[0];
    const float* mask   = (const float*)d_in[1];
    const float* w_attn = (const float*)d_in[2];
    const float* b_attn = (const float*)d_in[3];
    const float* w_proj = (const float*)d_in[4];
    const float* b_proj = (const float*)d_in[5];
    float* out = (float*)d_out;

    __nv_bfloat16 *hh, *hl, *qkvh, *qkvl, *ctxh, *ctxl, *vTh, *vTl, *wTh, *wTl, *pTh, *pTl;
    cudaGetSymbolAddress((void**)&hh,   g_hh);
    cudaGetSymbolAddress((void**)&hl,   g_hl);
    cudaGetSymbolAddress((void**)&qkvh, g_qkvh);
    cudaGetSymbolAddress((void**)&qkvl, g_qkvl);
    cudaGetSymbolAddress((void**)&ctxh, g_ctxh);
    cudaGetSymbolAddress((void**)&ctxl, g_ctxl);
    cudaGetSymbolAddress((void**)&vTh,  g_vTh);
    cudaGetSymbolAddress((void**)&vTl,  g_vTl);
    cudaGetSymbolAddress((void**)&wTh,  g_wTh);
    cudaGetSymbolAddress((void**)&wTl,  g_wTl);
    cudaGetSymbolAddress((void**)&pTh,  g_pTh);
    cudaGetSymbolAddress((void**)&pTl,  g_pTl);

    static bool attr_set = false;
    if (!attr_set) {
        cudaFuncSetAttribute(flash_attn_tc,
                             cudaFuncAttributeMaxDynamicSharedMemorySize, SMEM_TOT);
        cudaFuncSetAttribute(gemm_bf16_pipe,
                             cudaFuncAttributeMaxDynamicSharedMemorySize, G_SMEM);
        attr_set = true;
    }

    // 0) Fused prep (single launch)
    prep_all<<<8192, 256>>>(hidden, w_attn, w_proj, hh, hl, wTh, wTl, pTh, pTl);

    // 1) QKV GEMM -> split-bf16 qkv (Q/K) + transposed split V -> vT (fused)
    gemm_bf16_pipe<<<dim3(QKV_N / 128, M_TOT / 128), 256, G_SMEM>>>(
        hh, hl, wTh, wTl, b_attn, nullptr, qkvh, qkvl, vTh, vTl, HID, QKV_N);

    // 2) Flash attention -> split-bf16 ctx
    flash_attn_tc<<<dim3(SEQ / 256, NHEAD, BATCH), 512, SMEM_TOT>>>(
        qkvh, qkvl, vTh, vTl, mask, ctxh, ctxl);

    // 3) out = ctx @ c_proj_w + b
    gemm_bf16_pipe<<<dim3(HID / 128, M_TOT / 128), 256, G_SMEM>>>(
        ctxh, ctxl, pTh, pTl, b_proj, out, nullptr, nullptr, nullptr, nullptr, HID, HID);
}

// round 15
// speedup vs baseline: 1.1394x; 1.0768x over previous
#include <cuda_runtime.h>
#include <cuda_bf16.h>
#include <cstdint>

// Problem constants
#define BATCH   2
#define SEQ     2048
#define HID     1024
#define NHEAD   16
#define HDIM    64
#define QKV_N   (3 * HID)     // 3072
#define M_TOT   (BATCH * SEQ) // 4096

// Scratch (device globals: allocation-free rule)
__device__ __nv_bfloat16 g_hh[(size_t)M_TOT * HID];
__device__ __nv_bfloat16 g_hl[(size_t)M_TOT * HID];
__device__ __nv_bfloat16 g_qkvh[(size_t)M_TOT * QKV_N];
__device__ __nv_bfloat16 g_qkvl[(size_t)M_TOT * QKV_N];
__device__ __nv_bfloat16 g_ctxh[(size_t)M_TOT * HID];
__device__ __nv_bfloat16 g_ctxl[(size_t)M_TOT * HID];
__device__ __nv_bfloat16 g_vTh[(size_t)BATCH * HID * SEQ];
__device__ __nv_bfloat16 g_vTl[(size_t)BATCH * HID * SEQ];
__device__ __nv_bfloat16 g_wTh[(size_t)QKV_N * HID];
__device__ __nv_bfloat16 g_wTl[(size_t)QKV_N * HID];
__device__ __nv_bfloat16 g_pTh[(size_t)HID * HID];
__device__ __nv_bfloat16 g_pTl[(size_t)HID * HID];

// ---------------------------------------------------------------------------
// Helpers
// ---------------------------------------------------------------------------
__device__ __forceinline__ void split_bf16(float a, __nv_bfloat16& h, __nv_bfloat16& l) {
    h = __float2bfloat16_rn(a);
    l = __float2bfloat16_rn(a - __bfloat162float(h));
}

__device__ __forceinline__ void pack_split(float x, float y, uint32_t& hi, uint32_t& lo) {
    __nv_bfloat16 hx, lx, hy, ly;
    split_bf16(x, hx, lx);
    split_bf16(y, hy, ly);
    __nv_bfloat162 ph = {hx, hy}, pl = {lx, ly};
    hi = *(uint32_t*)&ph;
    lo = *(uint32_t*)&pl;
}

__device__ __forceinline__ void mma_bf16(
    float& d0, float& d1, float& d2, float& d3,
    uint32_t a0, uint32_t a1, uint32_t a2, uint32_t a3,
    uint32_t b0, uint32_t b1)
{
    asm volatile(
        "mma.sync.aligned.m16n8k16.row.col.f32.bf16.bf16.f32 "
        "{%0,%1,%2,%3}, {%4,%5,%6,%7}, {%8,%9}, {%0,%1,%2,%3};"
        : "+f"(d0), "+f"(d1), "+f"(d2), "+f"(d3)
        : "r"(a0), "r"(a1), "r"(a2), "r"(a3), "r"(b0), "r"(b1));
}

__device__ __forceinline__ void ldsm_x4(uint32_t& r0, uint32_t& r1, uint32_t& r2, uint32_t& r3,
                                        uint32_t addr)
{
    asm volatile("ldmatrix.sync.aligned.m8n8.x4.shared.b16 {%0,%1,%2,%3}, [%4];"
                 : "=r"(r0), "=r"(r1), "=r"(r2), "=r"(r3) : "r"(addr));
}

__device__ __forceinline__ uint32_t smem_u32(const void* p) {
    uint32_t a;
    asm("{ .reg .u64 t; cvta.to.shared.u64 t, %1; cvt.u32.u64 %0, t; }"
        : "=r"(a) : "l"(p));
    return a;
}

__device__ __forceinline__ void cp_async16(uint32_t dst, const void* src) {
    asm volatile("cp.async.ca.shared.global [%0], [%1], 16;" :: "r"(dst), "l"(src));
}
#define CP_COMMIT() asm volatile("cp.async.commit_group;" ::: "memory")
#define CP_WAIT(n)  asm volatile("cp.async.wait_group %0;" :: "n"(n) : "memory")

// ---------------------------------------------------------------------------
// Fused prep (round-13 proven)
// ---------------------------------------------------------------------------
__global__ __launch_bounds__(256) void prep_all(
    const float* __restrict__ hidden,
    const float* __restrict__ w_attn, const float* __restrict__ w_proj,
    __nv_bfloat16* __restrict__ hh,  __nv_bfloat16* __restrict__ hl,
    __nv_bfloat16* __restrict__ wTh, __nv_bfloat16* __restrict__ wTl,
    __nv_bfloat16* __restrict__ pTh, __nv_bfloat16* __restrict__ pTl)
{
    const int bid = blockIdx.x;
    const int tid = threadIdx.x;

    if (bid < 4096) {
        __shared__ float t[32][33];
        const float* B;
        __nv_bfloat16 *Bh, *Bl;
        int n0, k0, N, K;
        if (bid < 3072) {
            B = w_attn; Bh = wTh; Bl = wTl; N = QKV_N; K = HID;
            n0 = (bid % 96) * 32; k0 = (bid / 96) * 32;
        } else {
            const int b2 = bid - 3072;
            B = w_proj; Bh = pTh; Bl = pTl; N = HID; K = HID;
            n0 = (b2 % 32) * 32; k0 = (b2 / 32) * 32;
        }
        const int x = tid & 31, y = tid >> 5;
#pragma unroll
        for (int i = y; i < 32; i += 8)
            t[i][x] = B[(size_t)(k0 + i) * N + n0 + x];
        __syncthreads();
#pragma unroll
        for (int i = y; i < 32; i += 8) {
            float a = t[x][i];
            __nv_bfloat16 h, l;
            split_bf16(a, h, l);
            Bh[(size_t)(n0 + i) * K + k0 + x] = h;
            Bl[(size_t)(n0 + i) * K + k0 + x] = l;
        }
    } else {
        const size_t i = ((size_t)(bid - 4096) * 256 + tid) * 4;
        float4 v = *(const float4*)(hidden + i);
        uint32_t h0, l0, h1, l1;
        pack_split(v.x, v.y, h0, l0);
        pack_split(v.z, v.w, h1, l1);
        uint2 ph = {h0, h1}, pl = {l0, l1};
        *(uint2*)(hh + i) = ph;
        *(uint2*)(hl + i) = pl;
    }
}

// ---------------------------------------------------------------------------
// All-bf16 cp.async GEMM (round-14 proven, B-fragment double-buffering).
// ---------------------------------------------------------------------------
#define G_AH 0
#define G_AL 10240
#define G_BH 20480
#define G_BL 30720
#define G_STAGE 40960
#define G_SMEM (2 * G_STAGE)

__global__ __launch_bounds__(256, 2) void gemm_bf16_pipe(
    const __nv_bfloat16* __restrict__ Ah, const __nv_bfloat16* __restrict__ Al,
    const __nv_bfloat16* __restrict__ Bth, const __nv_bfloat16* __restrict__ Btl,
    const float* __restrict__ bias, float* __restrict__ C,
    __nv_bfloat16* __restrict__ Ch, __nv_bfloat16* __restrict__ Cl,
    __nv_bfloat16* __restrict__ VTh, __nv_bfloat16* __restrict__ VTl,
    int K, int N)
{
    extern __shared__ char smem[];
    const uint32_t smem_base = smem_u32(smem);

    const int tid = threadIdx.x;
    const int wid = tid >> 5;
    const int lane = tid & 31;
    const int g  = lane >> 2;
    const int c2 = (lane & 3) * 2;
    const int warp_m = wid & 1;
    const int warp_n = wid >> 1;
    const int m0 = blockIdx.y * 128;
    const int n0 = blockIdx.x * 128;
    const int wm = warp_m * 64;
    const int wn = warp_n * 32;

    const int lrA = lane & 15;
    const int lcA = (lane >> 4) * 8;
    uint32_t offA[4];
#pragma unroll
    for (int mi = 0; mi < 4; mi++)
        offA[mi] = (uint32_t)(((wm + mi * 16 + lrA) * 40 + lcA) * 2);
    uint32_t offB[2];
#pragma unroll
    for (int p = 0; p < 2; p++)
        offB[p] = (uint32_t)(((wn + p * 16 + ((lane >> 4) & 1) * 8 + (lane & 7)) * 40
                              + ((lane >> 3) & 1) * 8) * 2);

    float acc[4][4][4];
#pragma unroll
    for (int mi = 0; mi < 4; mi++)
#pragma unroll
        for (int ni = 0; ni < 4; ni++)
#pragma unroll
            for (int r = 0; r < 4; r++) acc[mi][ni][r] = 0.0f;

    auto issue = [&](int k0, int st) {
        const uint32_t sb = smem_base + st * G_STAGE;
#pragma unroll
        for (int it = 0; it < 2; it++) {
            const int idx = tid + it * 256;
            const int r = idx >> 2;
            const int q = idx & 3;
            const size_t aoff = (size_t)(m0 + r) * K + k0 + q * 8;
            const size_t boff = (size_t)(n0 + r) * K + k0 + q * 8;
            const uint32_t d = r * 80 + q * 16;
            cp_async16(sb + G_AH + d, Ah + aoff);
            cp_async16(sb + G_AL + d, Al + aoff);
            cp_async16(sb + G_BH + d, Bth + boff);
            cp_async16(sb + G_BL + d, Btl + boff);
        }
        CP_COMMIT();
    };

    const int nchunks = K >> 5;
    issue(0, 0);

    for (int ic = 0; ic < nchunks; ic++) {
        const int st = ic & 1;
        CP_WAIT(0);
        __syncthreads();
        if (ic + 1 < nchunks) issue((ic + 1) << 5, st ^ 1);

        const uint32_t sb = smem_base + st * G_STAGE;

        uint32_t bh[2][4], bl[2][4];
        ldsm_x4(bh[0][0], bh[0][1], bh[0][2], bh[0][3], sb + G_BH + offB[0]);
        ldsm_x4(bl[0][0], bl[0][1], bl[0][2], bl[0][3], sb + G_BL + offB[0]);
        int buf = 0;

#pragma unroll
        for (int kk = 0; kk < 32; kk += 16) {
            uint32_t ah[4][4], al[4][4];
#pragma unroll
            for (int mi = 0; mi < 4; mi++) {
                ldsm_x4(ah[mi][0], ah[mi][1], ah[mi][2], ah[mi][3],
                        sb + G_AH + offA[mi] + kk * 2);
                ldsm_x4(al[mi][0], al[mi][1], al[mi][2], al[mi][3],
                        sb + G_AL + offA[mi] + kk * 2);
            }
#pragma unroll
            for (int p = 0; p < 2; p++) {
                if (!(kk == 16 && p == 1)) {
                    const int nkk = (p == 1) ? kk + 16 : kk;
                    const int npp = (p == 1) ? 0 : 1;
                    ldsm_x4(bh[buf ^ 1][0], bh[buf ^ 1][1], bh[buf ^ 1][2], bh[buf ^ 1][3],
                            sb + G_BH + offB[npp] + nkk * 2);
                    ldsm_x4(bl[buf ^ 1][0], bl[buf ^ 1][1], bl[buf ^ 1][2], bl[buf ^ 1][3],
                            sb + G_BL + offB[npp] + nkk * 2);
                }
#pragma unroll
                for (int t = 0; t < 2; t++) {
                    const int ni = 2 * p + t;
                    const uint32_t bh0 = bh[buf][2 * t], bh1 = bh[buf][2 * t + 1];
                    const uint32_t bl0 = bl[buf][2 * t], bl1 = bl[buf][2 * t + 1];
#pragma unroll
                    for (int mi = 0; mi < 4; mi++) {
                        mma_bf16(acc[mi][ni][0], acc[mi][ni][1], acc[mi][ni][2], acc[mi][ni][3],
                                 ah[mi][0], ah[mi][1], ah[mi][2], ah[mi][3], bh0, bh1);
                        mma_bf16(acc[mi][ni][0], acc[mi][ni][1], acc[mi][ni][2], acc[mi][ni][3],
                                 ah[mi][0], ah[mi][1], ah[mi][2], ah[mi][3], bl0, bl1);
                        mma_bf16(acc[mi][ni][0], acc[mi][ni][1], acc[mi][ni][2], acc[mi][ni][3],
                                 al[mi][0], al[mi][1], al[mi][2], al[mi][3], bh0, bh1);
                    }
                }
                buf ^= 1;
            }
        }
    }

    if (Ch) {
        if (n0 >= 2 * HID) {
            __syncthreads();
            __nv_bfloat16* sH = (__nv_bfloat16*)smem;              // [128][136]
            __nv_bfloat16* sL = (__nv_bfloat16*)(smem + 34816);    // [128][136]
#pragma unroll
            for (int mi = 0; mi < 4; mi++) {
                const int r0 = wm + mi * 16 + g;
#pragma unroll
                for (int ni = 0; ni < 4; ni++) {
                    const int colL = wn + ni * 8 + c2;
                    const float b0 = __ldg(bias + n0 + colL);
                    const float b1 = __ldg(bias + n0 + colL + 1);
                    __nv_bfloat16 h, l;
                    float v;
                    v = acc[mi][ni][0] + b0; split_bf16(v, h, l);
                    sH[colL * 136 + r0] = h;           sL[colL * 136 + r0] = l;
                    v = acc[mi][ni][1] + b1; split_bf16(v, h, l);
                    sH[(colL + 1) * 136 + r0] = h;     sL[(colL + 1) * 136 + r0] = l;
                    v = acc[mi][ni][2] + b0; split_bf16(v, h, l);
                    sH[colL * 136 + r0 + 8] = h;       sL[colL * 136 + r0 + 8] = l;
                    v = acc[mi][ni][3] + b1; split_bf16(v, h, l);
                    sH[(colL + 1) * 136 + r0 + 8] = h; sL[(colL + 1) * 136 + r0 + 8] = l;
                }
            }
            __syncthreads();
            const int bidx  = m0 >> 11;
            const int s0    = m0 & (SEQ - 1);
            const int dbase = n0 - 2 * HID;
#pragma unroll
            for (int it = 0; it < 8; it++) {
                const int idx = tid + it * 256;
                const int d  = idx >> 4;
                const int ch = idx & 15;
                uint4 vh = *(const uint4*)(sH + d * 136 + ch * 8);
                uint4 vl = *(const uint4*)(sL + d * 136 + ch * 8);
                const size_t dst = ((size_t)bidx * HID + dbase + d) * SEQ + s0 + ch * 8;
                *(uint4*)(VTh + dst) = vh;
                *(uint4*)(VTl + dst) = vl;
            }
        } else {
#pragma unroll
            for (int mi = 0; mi < 4; mi++) {
                const int row0 = m0 + wm + mi * 16 + g;
#pragma unroll
                for (int ni = 0; ni < 4; ni++) {
                    const int colL = wn + ni * 8 + c2;
                    const float b0 = __ldg(bias + n0 + colL);
                    const float b1 = __ldg(bias + n0 + colL + 1);
                    uint32_t h0, l0, h1, l1;
                    pack_split(acc[mi][ni][0] + b0, acc[mi][ni][1] + b1, h0, l0);
                    pack_split(acc[mi][ni][2] + b0, acc[mi][ni][3] + b1, h1, l1);
                    const size_t o0 = (size_t)row0 * N + n0 + colL;
                    const size_t o1 = (size_t)(row0 + 8) * N + n0 + colL;
                    *(uint32_t*)(Ch + o0) = h0;
                    *(uint32_t*)(Cl + o0) = l0;
                    *(uint32_t*)(Ch + o1) = h1;
                    *(uint32_t*)(Cl + o1) = l1;
                }
            }
        }
    } else {
#pragma unroll
        for (int mi = 0; mi < 4; mi++) {
            const int row0 = m0 + wm + mi * 16 + g;
#pragma unroll
            for (int ni = 0; ni < 4; ni++) {
                const int colL = wn + ni * 8 + c2;
                const float b0 = __ldg(bias + n0 + colL);
                const float b1 = __ldg(bias + n0 + colL + 1);
                float2 v0 = {acc[mi][ni][0] + b0, acc[mi][ni][1] + b1};
                float2 v1 = {acc[mi][ni][2] + b0, acc[mi][ni][3] + b1};
                *(float2*)(C + (size_t)row0 * N + n0 + colL) = v0;
                *(float2*)(C + (size_t)(row0 + 8) * N + n0 + colL) = v1;
            }
        }
    }
}

// ===========================================================================
// Flash attention: 256 q-rows per CTA, 512 threads, 2-stage cp.async.
// QK uses 2-pass split (qh*kh + qh*kl); the ql*kh pass is DROPPED
// (score error ~5e-4 absolute, softmax-damped; Q-lo never loaded).
// PV keeps full 3-pass split with V-fragment double buffering.
// ===========================================================================
#define KH_OFF   0
#define KL_OFF   9216
#define VH_OFF   18432
#define VL_OFF   27648
#define STAGE_SZ 36864
#define MASK_OFF 73728
#define SMEM_TOT 74240

__global__ __launch_bounds__(512, 1) void flash_attn_tc(
    const __nv_bfloat16* __restrict__ qkvh, const __nv_bfloat16* __restrict__ qkvl,
    const __nv_bfloat16* __restrict__ vTh,  const __nv_bfloat16* __restrict__ vTl,
    const float* __restrict__ mask,
    __nv_bfloat16* __restrict__ ctxh, __nv_bfloat16* __restrict__ ctxl)
{
    extern __shared__ char smem[];
    const uint32_t smem_base = smem_u32(smem);

    const int tid  = threadIdx.x;
    const int wid  = tid >> 5;
    const int lane = tid & 31;
    const int g    = lane >> 2;
    const int c2   = (lane & 3) * 2;
    const int q0   = blockIdx.x * 256;
    const int h    = blockIdx.y;
    const int b    = blockIdx.z;

    const size_t row_base = (size_t)b * SEQ;
    const int hoff  = h * HDIM;
    const int khoff = HID + hoff;
    const size_t vrow_base = ((size_t)b * HID + hoff) * SEQ;

    uint32_t offKV[4];
#pragma unroll
    for (int p = 0; p < 4; p++)
        offKV[p] = (uint32_t)(((p * 16 + ((lane >> 4) & 1) * 8 + (lane & 7)) * 72
                               + ((lane >> 3) & 1) * 8) * 2);

    // Q fragments: hi part only (lo pass dropped)
    uint32_t qh[4][4];
    {
        const __nv_bfloat16* qr0 = qkvh + (row_base + q0 + wid * 16 + g) * QKV_N + hoff;
        const __nv_bfloat16* qr1 = qr0 + 8 * QKV_N;
#pragma unroll
        for (int s = 0; s < 4; s++) {
            qh[s][0] = *(const uint32_t*)(qr0 + s * 16 + c2);
            qh[s][1] = *(const uint32_t*)(qr1 + s * 16 + c2);
            qh[s][2] = *(const uint32_t*)(qr0 + s * 16 + 8 + c2);
            qh[s][3] = *(const uint32_t*)(qr1 + s * 16 + 8 + c2);
        }
    }

    float o[8][4];
#pragma unroll
    for (int j = 0; j < 8; j++)
#pragma unroll
        for (int r = 0; r < 4; r++) o[j][r] = 0.0f;
    float m0 = -1e30f, m1 = -1e30f, l0 = 0.0f, l1 = 0.0f;

    auto issue_tile = [&](int k0, int st) {
        const uint32_t sb = smem_base + st * STAGE_SZ;
#pragma unroll
        for (int it = 0; it < 2; it++) {
            const int idx = tid + it * 512;
            const int bufsel = idx >> 9;
            const int j = idx & 511;
            const int r = j >> 3;
            const int q = j & 7;
            const __nv_bfloat16* src =
                (bufsel ? qkvl : qkvh) + (row_base + k0 + r) * QKV_N + khoff + q * 8;
            cp_async16(sb + (bufsel ? KL_OFF : KH_OFF) + r * 144 + q * 16, src);
        }
#pragma unroll
        for (int it = 0; it < 2; it++) {
            const int idx = tid + it * 512;
            const int bufsel = idx >> 9;
            const int j = idx & 511;
            const int r = j >> 3;
            const int q = j & 7;
            const __nv_bfloat16* src =
                (bufsel ? vTl : vTh) + vrow_base + (size_t)r * SEQ + k0 + q * 8;
            cp_async16(sb + (bufsel ? VL_OFF : VH_OFF) + r * 144 + q * 16, src);
        }
        if (tid < 64)
            *(float*)(smem + MASK_OFF + st * 256 + tid * 4) = mask[(size_t)b * SEQ + k0 + tid];
        CP_COMMIT();
    };

    issue_tile(0, 0);

    for (int i = 0; i < SEQ / 64; i++) {
        const int st = i & 1;
        CP_WAIT(0);
        __syncthreads();
        if (i + 1 < SEQ / 64) issue_tile((i + 1) * 64, st ^ 1);

        const uint32_t sbKh = smem_base + st * STAGE_SZ + KH_OFF;
        const uint32_t sbKl = smem_base + st * STAGE_SZ + KL_OFF;
        const uint32_t sbVh = smem_base + st * STAGE_SZ + VH_OFF;
        const uint32_t sbVl = smem_base + st * STAGE_SZ + VL_OFF;
        const float* sMask = (const float*)(smem + MASK_OFF + st * 256);

        // ---- S = Q K^T: 2-pass (qh*kh + qh*kl) ----
        float sc[8][4];
#pragma unroll
        for (int j = 0; j < 8; j++)
#pragma unroll
            for (int r = 0; r < 4; r++) sc[j][r] = 0.0f;

#pragma unroll
        for (int s = 0; s < 4; s++) {
#pragma unroll
            for (int p = 0; p < 4; p++) {
                uint32_t bh[4], bl[4];
                ldsm_x4(bh[0], bh[1], bh[2], bh[3], sbKh + offKV[p] + s * 32);
                ldsm_x4(bl[0], bl[1], bl[2], bl[3], sbKl + offKV[p] + s * 32);
#pragma unroll
                for (int t = 0; t < 2; t++) {
                    const int j = 2 * p + t;
                    mma_bf16(sc[j][0], sc[j][1], sc[j][2], sc[j][3],
                             qh[s][0], qh[s][1], qh[s][2], qh[s][3], bh[2 * t], bh[2 * t + 1]);
                    mma_bf16(sc[j][0], sc[j][1], sc[j][2], sc[j][3],
                             qh[s][0], qh[s][1], qh[s][2], qh[s][3], bl[2 * t], bl[2 * t + 1]);
                }
            }
        }

        float rmax0 = -1e30f, rmax1 = -1e30f;
#pragma unroll
        for (int j = 0; j < 8; j++) {
            const float mv0 = sMask[j * 8 + c2];
            const float mv1 = sMask[j * 8 + c2 + 1];
            sc[j][0] = sc[j][0] * 0.125f + mv0;
            sc[j][1] = sc[j][1] * 0.125f + mv1;
            sc[j][2] = sc[j][2] * 0.125f + mv0;
            sc[j][3] = sc[j][3] * 0.125f + mv1;
            rmax0 = fmaxf(rmax0, fmaxf(sc[j][0], sc[j][1]));
            rmax1 = fmaxf(rmax1, fmaxf(sc[j][2], sc[j][3]));
        }
#pragma unroll
        for (int off = 1; off <= 2; off <<= 1) {
            rmax0 = fmaxf(rmax0, __shfl_xor_sync(0xffffffffu, rmax0, off));
            rmax1 = fmaxf(rmax1, __shfl_xor_sync(0xffffffffu, rmax1, off));
        }
        const float nm0 = fmaxf(m0, rmax0);
        const float nm1 = fmaxf(m1, rmax1);
        const float a0 = __expf(m0 - nm0);
        const float a1 = __expf(m1 - nm1);

        float rs0 = 0.0f, rs1 = 0.0f;
#pragma unroll
        for (int j = 0; j < 8; j++) {
            sc[j][0] = __expf(sc[j][0] - nm0);
            sc[j][1] = __expf(sc[j][1] - nm0);
            sc[j][2] = __expf(sc[j][2] - nm1);
            sc[j][3] = __expf(sc[j][3] - nm1);
            rs0 += sc[j][0] + sc[j][1];
            rs1 += sc[j][2] + sc[j][3];
        }
#pragma unroll
        for (int off = 1; off <= 2; off <<= 1) {
            rs0 += __shfl_xor_sync(0xffffffffu, rs0, off);
            rs1 += __shfl_xor_sync(0xffffffffu, rs1, off);
        }
        l0 = l0 * a0 + rs0;
        l1 = l1 * a1 + rs1;
        m0 = nm0;
        m1 = nm1;
#pragma unroll
        for (int j = 0; j < 8; j++) {
            o[j][0] *= a0; o[j][1] *= a0;
            o[j][2] *= a1; o[j][3] *= a1;
        }

        uint32_t ph[4][4], pl[4][4];
#pragma unroll
        for (int s = 0; s < 4; s++) {
            pack_split(sc[2 * s][0],     sc[2 * s][1],     ph[s][0], pl[s][0]);
            pack_split(sc[2 * s][2],     sc[2 * s][3],     ph[s][1], pl[s][1]);
            pack_split(sc[2 * s + 1][0], sc[2 * s + 1][1], ph[s][2], pl[s][2]);
            pack_split(sc[2 * s + 1][2], sc[2 * s + 1][3], ph[s][3], pl[s][3]);
        }

        // ---- O += P V (full 3-pass, V-fragment double buffer) ----
        {
            uint32_t vbh[2][4], vbl[2][4];
            ldsm_x4(vbh[0][0], vbh[0][1], vbh[0][2], vbh[0][3], sbVh + offKV[0]);
            ldsm_x4(vbl[0][0], vbl[0][1], vbl[0][2], vbl[0][3], sbVl + offKV[0]);
            int buf = 0;
#pragma unroll
            for (int s = 0; s < 4; s++) {
#pragma unroll
                for (int p = 0; p < 4; p++) {
                    if (!(s == 3 && p == 3)) {
                        const int ns = (p == 3) ? s + 1 : s;
                        const int np = (p == 3) ? 0 : p + 1;
                        ldsm_x4(vbh[buf ^ 1][0], vbh[buf ^ 1][1], vbh[buf ^ 1][2], vbh[buf ^ 1][3],
                                sbVh + offKV[np] + ns * 32);
                        ldsm_x4(vbl[buf ^ 1][0], vbl[buf ^ 1][1], vbl[buf ^ 1][2], vbl[buf ^ 1][3],
                                sbVl + offKV[np] + ns * 32);
                    }
#pragma unroll
                    for (int t = 0; t < 2; t++) {
                        const int j = 2 * p + t;
                        mma_bf16(o[j][0], o[j][1], o[j][2], o[j][3],
                                 ph[s][0], ph[s][1], ph[s][2], ph[s][3],
                                 vbh[buf][2 * t], vbh[buf][2 * t + 1]);
                        mma_bf16(o[j][0], o[j][1], o[j][2], o[j][3],
                                 ph[s][0], ph[s][1], ph[s][2], ph[s][3],
                                 vbl[buf][2 * t], vbl[buf][2 * t + 1]);
                        mma_bf16(o[j][0], o[j][1], o[j][2], o[j][3],
                                 pl[s][0], pl[s][1], pl[s][2], pl[s][3],
                                 vbh[buf][2 * t], vbh[buf][2 * t + 1]);
                    }
                    buf ^= 1;
                }
            }
        }
    }

    const float inv0 = 1.0f / l0;
    const float inv1 = 1.0f / l1;
    const size_t r0 = row_base + q0 + wid * 16 + g;
    const size_t r1 = r0 + 8;
#pragma unroll
    for (int j = 0; j < 8; j++) {
        uint32_t h0, lo0, h1, lo1;
        pack_split(o[j][0] * inv0, o[j][1] * inv0, h0, lo0);
        pack_split(o[j][2] * inv1, o[j][3] * inv1, h1, lo1);
        const size_t o0 = r0 * HID + hoff + j * 8 + c2;
        const size_t o1 = r1 * HID + hoff + j * 8 + c2;
        *(uint32_t*)(ctxh + o0) = h0;
        *(uint32_t*)(ctxl + o0) = lo0;
        *(uint32_t*)(ctxh + o1) = h1;
        *(uint32_t*)(ctxl + o1) = lo1;
    }
}

// ---------------------------------------------------------------------------
extern "C" void kernel_launch(void* const* d_in, const int* in_sizes, int n_in,
                              void* d_out, int out_size)
{
    const float* hidden = (const float*)d_in[0];
    const float* mask   = (const float*)d_in[1];
    const float* w_attn = (const float*)d_in[2];
    const float* b_attn = (const float*)d_in[3];
    const float* w_proj = (const float*)d_in[4];
    const float* b_proj = (const float*)d_in[5];
    float* out = (float*)d_out;

    __nv_bfloat16 *hh, *hl, *qkvh, *qkvl, *ctxh, *ctxl, *vTh, *vTl, *wTh, *wTl, *pTh, *pTl;
    cudaGetSymbolAddress((void**)&hh,   g_hh);
    cudaGetSymbolAddress((void**)&hl,   g_hl);
    cudaGetSymbolAddress((void**)&qkvh, g_qkvh);
    cudaGetSymbolAddress((void**)&qkvl, g_qkvl);
    cudaGetSymbolAddress((void**)&ctxh, g_ctxh);
    cudaGetSymbolAddress((void**)&ctxl, g_ctxl);
    cudaGetSymbolAddress((void**)&vTh,  g_vTh);
    cudaGetSymbolAddress((void**)&vTl,  g_vTl);
    cudaGetSymbolAddress((void**)&wTh,  g_wTh);
    cudaGetSymbolAddress((void**)&wTl,  g_wTl);
    cudaGetSymbolAddress((void**)&pTh,  g_pTh);
    cudaGetSymbolAddress((void**)&pTl,  g_pTl);

    static bool attr_set = false;
    if (!attr_set) {
        cudaFuncSetAttribute(flash_attn_tc,
                             cudaFuncAttributeMaxDynamicSharedMemorySize, SMEM_TOT);
        cudaFuncSetAttribute(gemm_bf16_pipe,
                             cudaFuncAttributeMaxDynamicSharedMemorySize, G_SMEM);
        attr_set = true;
    }

    // 0) Fused prep (single launch)
    prep_all<<<8192, 256>>>(hidden, w_attn, w_proj, hh, hl, wTh, wTl, pTh, pTl);

    // 1) QKV GEMM -> split-bf16 qkv (Q/K) + transposed split V -> vT (fused)
    gemm_bf16_pipe<<<dim3(QKV_N / 128, M_TOT / 128), 256, G_SMEM>>>(
        hh, hl, wTh, wTl, b_attn, nullptr, qkvh, qkvl, vTh, vTl, HID, QKV_N);

    // 2) Flash attention -> split-bf16 ctx
    flash_attn_tc<<<dim3(SEQ / 256, NHEAD, BATCH), 512, SMEM_TOT>>>(
        qkvh, qkvl, vTh, vTl, mask, ctxh, ctxl);

    // 3) out = ctx @ c_proj_w + b
    gemm_bf16_pipe<<<dim3(HID / 128, M_TOT / 128), 256, G_SMEM>>>(
        ctxh, ctxl, pTh, pTl, b_proj, out, nullptr, nullptr, nullptr, nullptr, HID, HID);
}

// round 16
// speedup vs baseline: 1.1407x; 1.0012x over previous
#include <cuda_runtime.h>
#include <cuda_bf16.h>
#include <cstdint>

// Problem constants
#define BATCH   2
#define SEQ     2048
#define HID     1024
#define NHEAD   16
#define HDIM    64
#define QKV_N   (3 * HID)     // 3072
#define M_TOT   (BATCH * SEQ) // 4096

// Scratch (device globals: allocation-free rule)
__device__ __nv_bfloat16 g_hh[(size_t)M_TOT * HID];
__device__ __nv_bfloat16 g_hl[(size_t)M_TOT * HID];
__device__ __nv_bfloat16 g_qkvh[(size_t)M_TOT * QKV_N];
__device__ __nv_bfloat16 g_qkvl[(size_t)M_TOT * QKV_N];
__device__ __nv_bfloat16 g_ctxh[(size_t)M_TOT * HID];
__device__ __nv_bfloat16 g_ctxl[(size_t)M_TOT * HID];
__device__ __nv_bfloat16 g_vTh[(size_t)BATCH * HID * SEQ];
__device__ __nv_bfloat16 g_vTl[(size_t)BATCH * HID * SEQ];
__device__ __nv_bfloat16 g_wTh[(size_t)QKV_N * HID];
__device__ __nv_bfloat16 g_wTl[(size_t)QKV_N * HID];
__device__ __nv_bfloat16 g_pTh[(size_t)HID * HID];
__device__ __nv_bfloat16 g_pTl[(size_t)HID * HID];

// ---------------------------------------------------------------------------
// Helpers
// ---------------------------------------------------------------------------
__device__ __forceinline__ void split_bf16(float a, __nv_bfloat16& h, __nv_bfloat16& l) {
    h = __float2bfloat16_rn(a);
    l = __float2bfloat16_rn(a - __bfloat162float(h));
}

__device__ __forceinline__ void pack_split(float x, float y, uint32_t& hi, uint32_t& lo) {
    __nv_bfloat16 hx, lx, hy, ly;
    split_bf16(x, hx, lx);
    split_bf16(y, hy, ly);
    __nv_bfloat162 ph = {hx, hy}, pl = {lx, ly};
    hi = *(uint32_t*)&ph;
    lo = *(uint32_t*)&pl;
}

__device__ __forceinline__ void mma_bf16(
    float& d0, float& d1, float& d2, float& d3,
    uint32_t a0, uint32_t a1, uint32_t a2, uint32_t a3,
    uint32_t b0, uint32_t b1)
{
    asm volatile(
        "mma.sync.aligned.m16n8k16.row.col.f32.bf16.bf16.f32 "
        "{%0,%1,%2,%3}, {%4,%5,%6,%7}, {%8,%9}, {%0,%1,%2,%3};"
        : "+f"(d0), "+f"(d1), "+f"(d2), "+f"(d3)
        : "r"(a0), "r"(a1), "r"(a2), "r"(a3), "r"(b0), "r"(b1));
}

__device__ __forceinline__ void ldsm_x4(uint32_t& r0, uint32_t& r1, uint32_t& r2, uint32_t& r3,
                                        uint32_t addr)
{
    asm volatile("ldmatrix.sync.aligned.m8n8.x4.shared.b16 {%0,%1,%2,%3}, [%4];"
                 : "=r"(r0), "=r"(r1), "=r"(r2), "=r"(r3) : "r"(addr));
}

__device__ __forceinline__ uint32_t smem_u32(const void* p) {
    uint32_t a;
    asm("{ .reg .u64 t; cvta.to.shared.u64 t, %1; cvt.u32.u64 %0, t; }"
        : "=r"(a) : "l"(p));
    return a;
}

__device__ __forceinline__ void cp_async16(uint32_t dst, const void* src) {
    asm volatile("cp.async.ca.shared.global [%0], [%1], 16;" :: "r"(dst), "l"(src));
}
#define CP_COMMIT() asm volatile("cp.async.commit_group;" ::: "memory")
#define CP_WAIT(n)  asm volatile("cp.async.wait_group %0;" :: "n"(n) : "memory")

// ---------------------------------------------------------------------------
// Fused prep (round-13 proven)
// ---------------------------------------------------------------------------
__global__ __launch_bounds__(256) void prep_all(
    const float* __restrict__ hidden,
    const float* __restrict__ w_attn, const float* __restrict__ w_proj,
    __nv_bfloat16* __restrict__ hh,  __nv_bfloat16* __restrict__ hl,
    __nv_bfloat16* __restrict__ wTh, __nv_bfloat16* __restrict__ wTl,
    __nv_bfloat16* __restrict__ pTh, __nv_bfloat16* __restrict__ pTl)
{
    const int bid = blockIdx.x;
    const int tid = threadIdx.x;

    if (bid < 4096) {
        __shared__ float t[32][33];
        const float* B;
        __nv_bfloat16 *Bh, *Bl;
        int n0, k0, N, K;
        if (bid < 3072) {
            B = w_attn; Bh = wTh; Bl = wTl; N = QKV_N; K = HID;
            n0 = (bid % 96) * 32; k0 = (bid / 96) * 32;
        } else {
            const int b2 = bid - 3072;
            B = w_proj; Bh = pTh; Bl = pTl; N = HID; K = HID;
            n0 = (b2 % 32) * 32; k0 = (b2 / 32) * 32;
        }
        const int x = tid & 31, y = tid >> 5;
#pragma unroll
        for (int i = y; i < 32; i += 8)
            t[i][x] = B[(size_t)(k0 + i) * N + n0 + x];
        __syncthreads();
#pragma unroll
        for (int i = y; i < 32; i += 8) {
            float a = t[x][i];
            __nv_bfloat16 h, l;
            split_bf16(a, h, l);
            Bh[(size_t)(n0 + i) * K + k0 + x] = h;
            Bl[(size_t)(n0 + i) * K + k0 + x] = l;
        }
    } else {
        const size_t i = ((size_t)(bid - 4096) * 256 + tid) * 4;
        float4 v = *(const float4*)(hidden + i);
        uint32_t h0, l0, h1, l1;
        pack_split(v.x, v.y, h0, l0);
        pack_split(v.z, v.w, h1, l1);
        uint2 ph = {h0, h1}, pl = {l0, l1};
        *(uint2*)(hh + i) = ph;
        *(uint2*)(hl + i) = pl;
    }
}

// ---------------------------------------------------------------------------
// All-bf16 cp.async GEMM (round-14 proven, B-fragment double-buffering).
// Q-region output tiles (n0 < HID when Ch!=null) are pre-scaled by 0.125
// (exact power-of-2: bit-identical to scaling the scores later).
// ---------------------------------------------------------------------------
#define G_AH 0
#define G_AL 10240
#define G_BH 20480
#define G_BL 30720
#define G_STAGE 40960
#define G_SMEM (2 * G_STAGE)

__global__ __launch_bounds__(256, 2) void gemm_bf16_pipe(
    const __nv_bfloat16* __restrict__ Ah, const __nv_bfloat16* __restrict__ Al,
    const __nv_bfloat16* __restrict__ Bth, const __nv_bfloat16* __restrict__ Btl,
    const float* __restrict__ bias, float* __restrict__ C,
    __nv_bfloat16* __restrict__ Ch, __nv_bfloat16* __restrict__ Cl,
    __nv_bfloat16* __restrict__ VTh, __nv_bfloat16* __restrict__ VTl,
    int K, int N)
{
    extern __shared__ char smem[];
    const uint32_t smem_base = smem_u32(smem);

    const int tid = threadIdx.x;
    const int wid = tid >> 5;
    const int lane = tid & 31;
    const int g  = lane >> 2;
    const int c2 = (lane & 3) * 2;
    const int warp_m = wid & 1;
    const int warp_n = wid >> 1;
    const int m0 = blockIdx.y * 128;
    const int n0 = blockIdx.x * 128;
    const int wm = warp_m * 64;
    const int wn = warp_n * 32;

    const int lrA = lane & 15;
    const int lcA = (lane >> 4) * 8;
    uint32_t offA[4];
#pragma unroll
    for (int mi = 0; mi < 4; mi++)
        offA[mi] = (uint32_t)(((wm + mi * 16 + lrA) * 40 + lcA) * 2);
    uint32_t offB[2];
#pragma unroll
    for (int p = 0; p < 2; p++)
        offB[p] = (uint32_t)(((wn + p * 16 + ((lane >> 4) & 1) * 8 + (lane & 7)) * 40
                              + ((lane >> 3) & 1) * 8) * 2);

    float acc[4][4][4];
#pragma unroll
    for (int mi = 0; mi < 4; mi++)
#pragma unroll
        for (int ni = 0; ni < 4; ni++)
#pragma unroll
            for (int r = 0; r < 4; r++) acc[mi][ni][r] = 0.0f;

    auto issue = [&](int k0, int st) {
        const uint32_t sb = smem_base + st * G_STAGE;
#pragma unroll
        for (int it = 0; it < 2; it++) {
            const int idx = tid + it * 256;
            const int r = idx >> 2;
            const int q = idx & 3;
            const size_t aoff = (size_t)(m0 + r) * K + k0 + q * 8;
            const size_t boff = (size_t)(n0 + r) * K + k0 + q * 8;
            const uint32_t d = r * 80 + q * 16;
            cp_async16(sb + G_AH + d, Ah + aoff);
            cp_async16(sb + G_AL + d, Al + aoff);
            cp_async16(sb + G_BH + d, Bth + boff);
            cp_async16(sb + G_BL + d, Btl + boff);
        }
        CP_COMMIT();
    };

    const int nchunks = K >> 5;
    issue(0, 0);

    for (int ic = 0; ic < nchunks; ic++) {
        const int st = ic & 1;
        CP_WAIT(0);
        __syncthreads();
        if (ic + 1 < nchunks) issue((ic + 1) << 5, st ^ 1);

        const uint32_t sb = smem_base + st * G_STAGE;

        uint32_t bh[2][4], bl[2][4];
        ldsm_x4(bh[0][0], bh[0][1], bh[0][2], bh[0][3], sb + G_BH + offB[0]);
        ldsm_x4(bl[0][0], bl[0][1], bl[0][2], bl[0][3], sb + G_BL + offB[0]);
        int buf = 0;

#pragma unroll
        for (int kk = 0; kk < 32; kk += 16) {
            uint32_t ah[4][4], al[4][4];
#pragma unroll
            for (int mi = 0; mi < 4; mi++) {
                ldsm_x4(ah[mi][0], ah[mi][1], ah[mi][2], ah[mi][3],
                        sb + G_AH + offA[mi] + kk * 2);
                ldsm_x4(al[mi][0], al[mi][1], al[mi][2], al[mi][3],
                        sb + G_AL + offA[mi] + kk * 2);
            }
#pragma unroll
            for (int p = 0; p < 2; p++) {
                if (!(kk == 16 && p == 1)) {
                    const int nkk = (p == 1) ? kk + 16 : kk;
                    const int npp = (p == 1) ? 0 : 1;
                    ldsm_x4(bh[buf ^ 1][0], bh[buf ^ 1][1], bh[buf ^ 1][2], bh[buf ^ 1][3],
                            sb + G_BH + offB[npp] + nkk * 2);
                    ldsm_x4(bl[buf ^ 1][0], bl[buf ^ 1][1], bl[buf ^ 1][2], bl[buf ^ 1][3],
                            sb + G_BL + offB[npp] + nkk * 2);
                }
#pragma unroll
                for (int t = 0; t < 2; t++) {
                    const int ni = 2 * p + t;
                    const uint32_t bh0 = bh[buf][2 * t], bh1 = bh[buf][2 * t + 1];
                    const uint32_t bl0 = bl[buf][2 * t], bl1 = bl[buf][2 * t + 1];
#pragma unroll
                    for (int mi = 0; mi < 4; mi++) {
                        mma_bf16(acc[mi][ni][0], acc[mi][ni][1], acc[mi][ni][2], acc[mi][ni][3],
                                 ah[mi][0], ah[mi][1], ah[mi][2], ah[mi][3], bh0, bh1);
                        mma_bf16(acc[mi][ni][0], acc[mi][ni][1], acc[mi][ni][2], acc[mi][ni][3],
                                 ah[mi][0], ah[mi][1], ah[mi][2], ah[mi][3], bl0, bl1);
                        mma_bf16(acc[mi][ni][0], acc[mi][ni][1], acc[mi][ni][2], acc[mi][ni][3],
                                 al[mi][0], al[mi][1], al[mi][2], al[mi][3], bh0, bh1);
                    }
                }
                buf ^= 1;
            }
        }
    }

    if (Ch) {
        if (n0 >= 2 * HID) {
            __syncthreads();
            __nv_bfloat16* sH = (__nv_bfloat16*)smem;              // [128][136]
            __nv_bfloat16* sL = (__nv_bfloat16*)(smem + 34816);    // [128][136]
#pragma unroll
            for (int mi = 0; mi < 4; mi++) {
                const int r0 = wm + mi * 16 + g;
#pragma unroll
                for (int ni = 0; ni < 4; ni++) {
                    const int colL = wn + ni * 8 + c2;
                    const float b0 = __ldg(bias + n0 + colL);
                    const float b1 = __ldg(bias + n0 + colL + 1);
                    __nv_bfloat16 h, l;
                    float v;
                    v = acc[mi][ni][0] + b0; split_bf16(v, h, l);
                    sH[colL * 136 + r0] = h;           sL[colL * 136 + r0] = l;
                    v = acc[mi][ni][1] + b1; split_bf16(v, h, l);
                    sH[(colL + 1) * 136 + r0] = h;     sL[(colL + 1) * 136 + r0] = l;
                    v = acc[mi][ni][2] + b0; split_bf16(v, h, l);
                    sH[colL * 136 + r0 + 8] = h;       sL[colL * 136 + r0 + 8] = l;
                    v = acc[mi][ni][3] + b1; split_bf16(v, h, l);
                    sH[(colL + 1) * 136 + r0 + 8] = h; sL[(colL + 1) * 136 + r0 + 8] = l;
                }
            }
            __syncthreads();
            const int bidx  = m0 >> 11;
            const int s0    = m0 & (SEQ - 1);
            const int dbase = n0 - 2 * HID;
#pragma unroll
            for (int it = 0; it < 8; it++) {
                const int idx = tid + it * 256;
                const int d  = idx >> 4;
                const int ch = idx & 15;
                uint4 vh = *(const uint4*)(sH + d * 136 + ch * 8);
                uint4 vl = *(const uint4*)(sL + d * 136 + ch * 8);
                const size_t dst = ((size_t)bidx * HID + dbase + d) * SEQ + s0 + ch * 8;
                *(uint4*)(VTh + dst) = vh;
                *(uint4*)(VTl + dst) = vl;
            }
        } else {
            // Q region pre-scaled by 0.125 (exact power of 2; bit-identical
            // to applying the scale to the scores later). K region scale 1.
            const float scl = (n0 < HID) ? 0.125f : 1.0f;
#pragma unroll
            for (int mi = 0; mi < 4; mi++) {
                const int row0 = m0 + wm + mi * 16 + g;
#pragma unroll
                for (int ni = 0; ni < 4; ni++) {
                    const int colL = wn + ni * 8 + c2;
                    const float b0 = __ldg(bias + n0 + colL);
                    const float b1 = __ldg(bias + n0 + colL + 1);
                    uint32_t h0, l0, h1, l1;
                    pack_split((acc[mi][ni][0] + b0) * scl, (acc[mi][ni][1] + b1) * scl, h0, l0);
                    pack_split((acc[mi][ni][2] + b0) * scl, (acc[mi][ni][3] + b1) * scl, h1, l1);
                    const size_t o0 = (size_t)row0 * N + n0 + colL;
                    const size_t o1 = (size_t)(row0 + 8) * N + n0 + colL;
                    *(uint32_t*)(Ch + o0) = h0;
                    *(uint32_t*)(Cl + o0) = l0;
                    *(uint32_t*)(Ch + o1) = h1;
                    *(uint32_t*)(Cl + o1) = l1;
                }
            }
        }
    } else {
#pragma unroll
        for (int mi = 0; mi < 4; mi++) {
            const int row0 = m0 + wm + mi * 16 + g;
#pragma unroll
            for (int ni = 0; ni < 4; ni++) {
                const int colL = wn + ni * 8 + c2;
                const float b0 = __ldg(bias + n0 + colL);
                const float b1 = __ldg(bias + n0 + colL + 1);
                float2 v0 = {acc[mi][ni][0] + b0, acc[mi][ni][1] + b1};
                float2 v1 = {acc[mi][ni][2] + b0, acc[mi][ni][3] + b1};
                *(float2*)(C + (size_t)row0 * N + n0 + colL) = v0;
                *(float2*)(C + (size_t)(row0 + 8) * N + n0 + colL) = v1;
            }
        }
    }
}

// ===========================================================================
// Flash attention: 256 q-rows per CTA, 512 threads, 2-stage cp.async.
// QK 2-pass (qh*kh + qh*kl), Q pre-scaled in GEMM epilogue (no score FMUL).
// K-fragment AND V-fragment double buffering.
// ===========================================================================
#define KH_OFF   0
#define KL_OFF   9216
#define VH_OFF   18432
#define VL_OFF   27648
#define STAGE_SZ 36864
#define MASK_OFF 73728
#define SMEM_TOT 74240

__global__ __launch_bounds__(512, 1) void flash_attn_tc(
    const __nv_bfloat16* __restrict__ qkvh, const __nv_bfloat16* __restrict__ qkvl,
    const __nv_bfloat16* __restrict__ vTh,  const __nv_bfloat16* __restrict__ vTl,
    const float* __restrict__ mask,
    __nv_bfloat16* __restrict__ ctxh, __nv_bfloat16* __restrict__ ctxl)
{
    extern __shared__ char smem[];
    const uint32_t smem_base = smem_u32(smem);

    const int tid  = threadIdx.x;
    const int wid  = tid >> 5;
    const int lane = tid & 31;
    const int g    = lane >> 2;
    const int c2   = (lane & 3) * 2;
    const int q0   = blockIdx.x * 256;
    const int h    = blockIdx.y;
    const int b    = blockIdx.z;

    const size_t row_base = (size_t)b * SEQ;
    const int hoff  = h * HDIM;
    const int khoff = HID + hoff;
    const size_t vrow_base = ((size_t)b * HID + hoff) * SEQ;

    uint32_t offKV[4];
#pragma unroll
    for (int p = 0; p < 4; p++)
        offKV[p] = (uint32_t)(((p * 16 + ((lane >> 4) & 1) * 8 + (lane & 7)) * 72
                               + ((lane >> 3) & 1) * 8) * 2);

    // Q fragments: hi part only (pre-scaled by 0.125 in GEMM epilogue)
    uint32_t qh[4][4];
    {
        const __nv_bfloat16* qr0 = qkvh + (row_base + q0 + wid * 16 + g) * QKV_N + hoff;
        const __nv_bfloat16* qr1 = qr0 + 8 * QKV_N;
#pragma unroll
        for (int s = 0; s < 4; s++) {
            qh[s][0] = *(const uint32_t*)(qr0 + s * 16 + c2);
            qh[s][1] = *(const uint32_t*)(qr1 + s * 16 + c2);
            qh[s][2] = *(const uint32_t*)(qr0 + s * 16 + 8 + c2);
            qh[s][3] = *(const uint32_t*)(qr1 + s * 16 + 8 + c2);
        }
    }

    float o[8][4];
#pragma unroll
    for (int j = 0; j < 8; j++)
#pragma unroll
        for (int r = 0; r < 4; r++) o[j][r] = 0.0f;
    float m0 = -1e30f, m1 = -1e30f, l0 = 0.0f, l1 = 0.0f;

    auto issue_tile = [&](int k0, int st) {
        const uint32_t sb = smem_base + st * STAGE_SZ;
#pragma unroll
        for (int it = 0; it < 2; it++) {
            const int idx = tid + it * 512;
            const int bufsel = idx >> 9;
            const int j = idx & 511;
            const int r = j >> 3;
            const int q = j & 7;
            const __nv_bfloat16* src =
                (bufsel ? qkvl : qkvh) + (row_base + k0 + r) * QKV_N + khoff + q * 8;
            cp_async16(sb + (bufsel ? KL_OFF : KH_OFF) + r * 144 + q * 16, src);
        }
#pragma unroll
        for (int it = 0; it < 2; it++) {
            const int idx = tid + it * 512;
            const int bufsel = idx >> 9;
            const int j = idx & 511;
            const int r = j >> 3;
            const int q = j & 7;
            const __nv_bfloat16* src =
                (bufsel ? vTl : vTh) + vrow_base + (size_t)r * SEQ + k0 + q * 8;
            cp_async16(sb + (bufsel ? VL_OFF : VH_OFF) + r * 144 + q * 16, src);
        }
        if (tid < 64)
            *(float*)(smem + MASK_OFF + st * 256 + tid * 4) = mask[(size_t)b * SEQ + k0 + tid];
        CP_COMMIT();
    };

    issue_tile(0, 0);

    for (int i = 0; i < SEQ / 64; i++) {
        const int st = i & 1;
        CP_WAIT(0);
        __syncthreads();
        if (i + 1 < SEQ / 64) issue_tile((i + 1) * 64, st ^ 1);

        const uint32_t sbKh = smem_base + st * STAGE_SZ + KH_OFF;
        const uint32_t sbKl = smem_base + st * STAGE_SZ + KL_OFF;
        const uint32_t sbVh = smem_base + st * STAGE_SZ + VH_OFF;
        const uint32_t sbVl = smem_base + st * STAGE_SZ + VL_OFF;
        const float* sMask = (const float*)(smem + MASK_OFF + st * 256);

        // ---- S = Q K^T: 2-pass (qh*kh + qh*kl), K-fragment double buffer ----
        float sc[8][4];
#pragma unroll
        for (int j = 0; j < 8; j++)
#pragma unroll
            for (int r = 0; r < 4; r++) sc[j][r] = 0.0f;

        {
            uint32_t kbh[2][4], kbl[2][4];
            ldsm_x4(kbh[0][0], kbh[0][1], kbh[0][2], kbh[0][3], sbKh + offKV[0]);
            ldsm_x4(kbl[0][0], kbl[0][1], kbl[0][2], kbl[0][3], sbKl + offKV[0]);
            int buf = 0;
#pragma unroll
            for (int s = 0; s < 4; s++) {
#pragma unroll
                for (int p = 0; p < 4; p++) {
                    if (!(s == 3 && p == 3)) {
                        const int ns = (p == 3) ? s + 1 : s;
                        const int np = (p == 3) ? 0 : p + 1;
                        ldsm_x4(kbh[buf ^ 1][0], kbh[buf ^ 1][1], kbh[buf ^ 1][2], kbh[buf ^ 1][3],
                                sbKh + offKV[np] + ns * 32);
                        ldsm_x4(kbl[buf ^ 1][0], kbl[buf ^ 1][1], kbl[buf ^ 1][2], kbl[buf ^ 1][3],
                                sbKl + offKV[np] + ns * 32);
                    }
#pragma unroll
                    for (int t = 0; t < 2; t++) {
                        const int j = 2 * p + t;
                        mma_bf16(sc[j][0], sc[j][1], sc[j][2], sc[j][3],
                                 qh[s][0], qh[s][1], qh[s][2], qh[s][3],
                                 kbh[buf][2 * t], kbh[buf][2 * t + 1]);
                        mma_bf16(sc[j][0], sc[j][1], sc[j][2], sc[j][3],
                                 qh[s][0], qh[s][1], qh[s][2], qh[s][3],
                                 kbl[buf][2 * t], kbl[buf][2 * t + 1]);
                    }
                    buf ^= 1;
                }
            }
        }

        float rmax0 = -1e30f, rmax1 = -1e30f;
#pragma unroll
        for (int j = 0; j < 8; j++) {
            const float mv0 = sMask[j * 8 + c2];
            const float mv1 = sMask[j * 8 + c2 + 1];
            sc[j][0] = sc[j][0] + mv0;
            sc[j][1] = sc[j][1] + mv1;
            sc[j][2] = sc[j][2] + mv0;
            sc[j][3] = sc[j][3] + mv1;
            rmax0 = fmaxf(rmax0, fmaxf(sc[j][0], sc[j][1]));
            rmax1 = fmaxf(rmax1, fmaxf(sc[j][2], sc[j][3]));
        }
#pragma unroll
        for (int off = 1; off <= 2; off <<= 1) {
            rmax0 = fmaxf(rmax0, __shfl_xor_sync(0xffffffffu, rmax0, off));
            rmax1 = fmaxf(rmax1, __shfl_xor_sync(0xffffffffu, rmax1, off));
        }
        const float nm0 = fmaxf(m0, rmax0);
        const float nm1 = fmaxf(m1, rmax1);
        const float a0 = __expf(m0 - nm0);
        const float a1 = __expf(m1 - nm1);

        float rs0 = 0.0f, rs1 = 0.0f;
#pragma unroll
        for (int j = 0; j < 8; j++) {
            sc[j][0] = __expf(sc[j][0] - nm0);
            sc[j][1] = __expf(sc[j][1] - nm0);
            sc[j][2] = __expf(sc[j][2] - nm1);
            sc[j][3] = __expf(sc[j][3] - nm1);
            rs0 += sc[j][0] + sc[j][1];
            rs1 += sc[j][2] + sc[j][3];
        }
#pragma unroll
        for (int off = 1; off <= 2; off <<= 1) {
            rs0 += __shfl_xor_sync(0xffffffffu, rs0, off);
            rs1 += __shfl_xor_sync(0xffffffffu, rs1, off);
        }
        l0 = l0 * a0 + rs0;
        l1 = l1 * a1 + rs1;
        m0 = nm0;
        m1 = nm1;
#pragma unroll
        for (int j = 0; j < 8; j++) {
            o[j][0] *= a0; o[j][1] *= a0;
            o[j][2] *= a1; o[j][3] *= a1;
        }

        uint32_t ph[4][4], pl[4][4];
#pragma unroll
        for (int s = 0; s < 4; s++) {
            pack_split(sc[2 * s][0],     sc[2 * s][1],     ph[s][0], pl[s][0]);
            pack_split(sc[2 * s][2],     sc[2 * s][3],     ph[s][1], pl[s][1]);
            pack_split(sc[2 * s + 1][0], sc[2 * s + 1][1], ph[s][2], pl[s][2]);
            pack_split(sc[2 * s + 1][2], sc[2 * s + 1][3], ph[s][3], pl[s][3]);
        }

        // ---- O += P V (full 3-pass, V-fragment double buffer) ----
        {
            uint32_t vbh[2][4], vbl[2][4];
            ldsm_x4(vbh[0][0], vbh[0][1], vbh[0][2], vbh[0][3], sbVh + offKV[0]);
            ldsm_x4(vbl[0][0], vbl[0][1], vbl[0][2], vbl[0][3], sbVl + offKV[0]);
            int buf = 0;
#pragma unroll
            for (int s = 0; s < 4; s++) {
#pragma unroll
                for (int p = 0; p < 4; p++) {
                    if (!(s == 3 && p == 3)) {
                        const int ns = (p == 3) ? s + 1 : s;
                        const int np = (p == 3) ? 0 : p + 1;
                        ldsm_x4(vbh[buf ^ 1][0], vbh[buf ^ 1][1], vbh[buf ^ 1][2], vbh[buf ^ 1][3],
                                sbVh + offKV[np] + ns * 32);
                        ldsm_x4(vbl[buf ^ 1][0], vbl[buf ^ 1][1], vbl[buf ^ 1][2], vbl[buf ^ 1][3],
                                sbVl + offKV[np] + ns * 32);
                    }
#pragma unroll
                    for (int t = 0; t < 2; t++) {
                        const int j = 2 * p + t;
                        mma_bf16(o[j][0], o[j][1], o[j][2], o[j][3],
                                 ph[s][0], ph[s][1], ph[s][2], ph[s][3],
                                 vbh[buf][2 * t], vbh[buf][2 * t + 1]);
                        mma_bf16(o[j][0], o[j][1], o[j][2], o[j][3],
                                 ph[s][0], ph[s][1], ph[s][2], ph[s][3],
                                 vbl[buf][2 * t], vbl[buf][2 * t + 1]);
                        mma_bf16(o[j][0], o[j][1], o[j][2], o[j][3],
                                 pl[s][0], pl[s][1], pl[s][2], pl[s][3],
                                 vbh[buf][2 * t], vbh[buf][2 * t + 1]);
                    }
                    buf ^= 1;
                }
            }
        }
    }

    const float inv0 = 1.0f / l0;
    const float inv1 = 1.0f / l1;
    const size_t r0 = row_base + q0 + wid * 16 + g;
    const size_t r1 = r0 + 8;
#pragma unroll
    for (int j = 0; j < 8; j++) {
        uint32_t h0, lo0, h1, lo1;
        pack_split(o[j][0] * inv0, o[j][1] * inv0, h0, lo0);
        pack_split(o[j][2] * inv1, o[j][3] * inv1, h1, lo1);
        const size_t o0 = r0 * HID + hoff + j * 8 + c2;
        const size_t o1 = r1 * HID + hoff + j * 8 + c2;
        *(uint32_t*)(ctxh + o0) = h0;
        *(uint32_t*)(ctxl + o0) = lo0;
        *(uint32_t*)(ctxh + o1) = h1;
        *(uint32_t*)(ctxl + o1) = lo1;
    }
}

// ---------------------------------------------------------------------------
extern "C" void kernel_launch(void* const* d_in, const int* in_sizes, int n_in,
                              void* d_out, int out_size)
{
    const float* hidden = (const float*)d_in[0];
    const float* mask   = (const float*)d_in[1];
    const float* w_attn = (const float*)d_in[2];
    const float* b_attn = (const float*)d_in[3];
    const float* w_proj = (const float*)d_in[4];
    const float* b_proj = (const float*)d_in[5];
    float* out = (float*)d_out;

    __nv_bfloat16 *hh, *hl, *qkvh, *qkvl, *ctxh, *ctxl, *vTh, *vTl, *wTh, *wTl, *pTh, *pTl;
    cudaGetSymbolAddress((void**)&hh,   g_hh);
    cudaGetSymbolAddress((void**)&hl,   g_hl);
    cudaGetSymbolAddress((void**)&qkvh, g_qkvh);
    cudaGetSymbolAddress((void**)&qkvl, g_qkvl);
    cudaGetSymbolAddress((void**)&ctxh, g_ctxh);
    cudaGetSymbolAddress((void**)&ctxl, g_ctxl);
    cudaGetSymbolAddress((void**)&vTh,  g_vTh);
    cudaGetSymbolAddress((void**)&vTl,  g_vTl);
    cudaGetSymbolAddress((void**)&wTh,  g_wTh);
    cudaGetSymbolAddress((void**)&wTl,  g_wTl);
    cudaGetSymbolAddress((void**)&pTh,  g_pTh);
    cudaGetSymbolAddress((void**)&pTl,  g_pTl);

    static bool attr_set = false;
    if (!attr_set) {
        cudaFuncSetAttribute(flash_attn_tc,
                             cudaFuncAttributeMaxDynamicSharedMemorySize, SMEM_TOT);
        cudaFuncSetAttribute(gemm_bf16_pipe,
                             cudaFuncAttributeMaxDynamicSharedMemorySize, G_SMEM);
        attr_set = true;
    }

    // 0) Fused prep (single launch)
    prep_all<<<8192, 256>>>(hidden, w_attn, w_proj, hh, hl, wTh, wTl, pTh, pTl);

    // 1) QKV GEMM -> split-bf16 qkv (Q pre-scaled, K) + transposed split V -> vT
    gemm_bf16_pipe<<<dim3(QKV_N / 128, M_TOT / 128), 256, G_SMEM>>>(
        hh, hl, wTh, wTl, b_attn, nullptr, qkvh, qkvl, vTh, vTl, HID, QKV_N);

    // 2) Flash attention -> split-bf16 ctx
    flash_attn_tc<<<dim3(SEQ / 256, NHEAD, BATCH), 512, SMEM_TOT>>>(
        qkvh, qkvl, vTh, vTl, mask, ctxh, ctxl);

    // 3) out = ctx @ c_proj_w + b
    gemm_bf16_pipe<<<dim3(HID / 128, M_TOT / 128), 256, G_SMEM>>>(
        ctxh, ctxl, pTh, pTl, b_proj, out, nullptr, nullptr, nullptr, nullptr, HID, HID);
}